// round 2
// baseline (speedup 1.0000x reference)
#include <cuda_runtime.h>
#include <cstdint>

// Problem constants (fixed shapes per reference)
#define K_BLOCKS 1024
#define NROWBLK  64      // OUT / BS
#define BS       64
#define TM       128     // N-rows per CTA tile
#define IN_DIM   4096
#define OUT_DIM  4096
#define N_DIM    4096
#define SX       65      // padded smem stride for x tile
#define SW       65      // padded smem stride for w tile

// Scratch: per-output-block-row lists of contributing sparse blocks.
__device__ int g_row_cnt[NROWBLK];
__device__ int g_row_list[NROWBLK * K_BLOCKS];

// One warp per output block-row; deterministic (k-ordered) binning via ballot.
__global__ void build_rows_kernel(const int* __restrict__ row_idx) {
    int r = blockIdx.x;
    int lane = threadIdx.x;
    int cnt = 0;
    for (int base = 0; base < K_BLOCKS; base += 32) {
        int k = base + lane;
        int v = row_idx[k];
        unsigned m = __ballot_sync(0xffffffffu, v == r);
        if (v == r) {
            int pos = __popc(m & ((1u << lane) - 1u));
            g_row_list[r * K_BLOCKS + cnt + pos] = k;
        }
        cnt += __popc(m);
    }
    if (lane == 0) g_row_cnt[r] = cnt;
}

extern __shared__ float smem_dyn[];

// Main block-sparse kernel.
// grid = (N/TM, NROWBLK), block = 256.
// CTA computes y[n0:n0+128, r*64:(r+1)*64] = bias + sum over blocks in row r.
__global__ __launch_bounds__(256, 3) void bsl_main_kernel(
    const float* __restrict__ x,
    const float* __restrict__ blocks,
    const float* __restrict__ bias,
    const int* __restrict__ col_idx,
    float* __restrict__ y)
{
    float* xs = smem_dyn;               // [TM][SX]
    float* ws = smem_dyn + TM * SX;     // [BS][SW]

    const int r   = blockIdx.y;
    const int n0  = blockIdx.x * TM;
    const int tid = threadIdx.x;
    const int tx8 = (tid & 7) * 8;      // output col group (8 cols)
    const int ty4 = (tid >> 3) * 4;     // row group (4 rows)

    const int cnt = g_row_cnt[r];
    const int* list = g_row_list + r * K_BLOCKS;

    // Init accumulators with bias (bias depends only on output column).
    float acc[4][8];
    #pragma unroll
    for (int cc = 0; cc < 8; cc++) {
        float b = bias[r * BS + tx8 + cc];
        #pragma unroll
        for (int rr = 0; rr < 4; rr++) acc[rr][cc] = b;
    }

    for (int it = 0; it < cnt; it++) {
        const int k  = list[it];
        const int cb = col_idx[k];

        // Stage x tile [128 x 64] -> xs (padded). 2048 float4s, 8 per thread.
        const float4* xg = reinterpret_cast<const float4*>(
            x + (size_t)n0 * IN_DIM + (size_t)cb * BS);
        #pragma unroll
        for (int u = 0; u < 8; u++) {
            int f   = tid + u * 256;     // 0..2047
            int row = f >> 4;
            int c4  = f & 15;
            float4 v = xg[(size_t)row * (IN_DIM / 4) + c4];
            float* d = xs + row * SX + c4 * 4;
            d[0] = v.x; d[1] = v.y; d[2] = v.z; d[3] = v.w;
        }

        // Stage weight tile blocks[k] [64 x 64] -> ws (padded). 1024 float4s.
        const float4* wg = reinterpret_cast<const float4*>(
            blocks + (size_t)k * (BS * BS));
        #pragma unroll
        for (int u = 0; u < 4; u++) {
            int f  = tid + u * 256;      // 0..1023
            int o  = f >> 4;
            int i4 = f & 15;
            float4 v = wg[f];
            float* d = ws + o * SW + i4 * 4;
            d[0] = v.x; d[1] = v.y; d[2] = v.z; d[3] = v.w;
        }
        __syncthreads();

        // acc[rr][cc] += sum_i xs[ty4+rr][i] * ws[tx8+cc][i]
        #pragma unroll 8
        for (int i = 0; i < BS; i++) {
            float xv[4], wv[8];
            #pragma unroll
            for (int rr = 0; rr < 4; rr++) xv[rr] = xs[(ty4 + rr) * SX + i];
            #pragma unroll
            for (int cc = 0; cc < 8; cc++) wv[cc] = ws[(tx8 + cc) * SW + i];
            #pragma unroll
            for (int rr = 0; rr < 4; rr++)
                #pragma unroll
                for (int cc = 0; cc < 8; cc++)
                    acc[rr][cc] = fmaf(xv[rr], wv[cc], acc[rr][cc]);
        }
        __syncthreads();
    }

    // Store y tile (every element written -> handles 0xAA poison + bias-only rows).
    #pragma unroll
    for (int rr = 0; rr < 4; rr++) {
        float4 v0 = make_float4(acc[rr][0], acc[rr][1], acc[rr][2], acc[rr][3]);
        float4 v1 = make_float4(acc[rr][4], acc[rr][5], acc[rr][6], acc[rr][7]);
        float4* out = reinterpret_cast<float4*>(
            y + (size_t)(n0 + ty4 + rr) * OUT_DIM + r * BS + tx8);
        out[0] = v0;
        out[1] = v1;
    }
}

extern "C" void kernel_launch(void* const* d_in, const int* in_sizes, int n_in,
                              void* d_out, int out_size) {
    (void)in_sizes; (void)n_in; (void)out_size;
    const float* x       = (const float*)d_in[0];
    const float* blocks  = (const float*)d_in[1];
    const float* bias    = (const float*)d_in[2];
    const int*   row_idx = (const int*)d_in[3];
    const int*   col_idx = (const int*)d_in[4];
    float*       y       = (float*)d_out;

    const int smem_bytes = (TM * SX + BS * SW) * sizeof(float);  // 49920 B
    cudaFuncSetAttribute(bsl_main_kernel,
                         cudaFuncAttributeMaxDynamicSharedMemorySize, smem_bytes);

    build_rows_kernel<<<NROWBLK, 32>>>(row_idx);

    dim3 grid(N_DIM / TM, NROWBLK);
    bsl_main_kernel<<<grid, 256, smem_bytes>>>(x, blocks, bias, col_idx, y);
}

// round 3
// speedup vs baseline: 3.6785x; 3.6785x over previous
#include <cuda_runtime.h>
#include <cuda_bf16.h>
#include <cstdint>

// Problem constants (fixed shapes per reference)
#define K_BLOCKS 1024
#define NROWBLK  64      // OUT / BS
#define BS       64
#define TM       128     // N-rows per CTA tile
#define IN_DIM   4096
#define OUT_DIM  4096
#define N_DIM    4096
#define SSTRIDE  72      // padded bf16 smem row stride (72*2=144B -> conflict-free ldmatrix)

// ---------------- scratch (__device__ globals; no allocs allowed) ----------------
__device__ int g_row_cnt[NROWBLK];
__device__ int g_row_list[NROWBLK * K_BLOCKS];
__device__ __nv_bfloat16 g_xh[(size_t)N_DIM * IN_DIM];
__device__ __nv_bfloat16 g_xl[(size_t)N_DIM * IN_DIM];
__device__ __nv_bfloat16 g_wh[(size_t)K_BLOCKS * BS * BS];
__device__ __nv_bfloat16 g_wl[(size_t)K_BLOCKS * BS * BS];

// ---------------- row binning (one warp per output block-row) ----------------
__global__ void build_rows_kernel(const int* __restrict__ row_idx) {
    int r = blockIdx.x;
    int lane = threadIdx.x;
    int cnt = 0;
    for (int base = 0; base < K_BLOCKS; base += 32) {
        int k = base + lane;
        int v = row_idx[k];
        unsigned m = __ballot_sync(0xffffffffu, v == r);
        if (v == r) {
            int pos = __popc(m & ((1u << lane) - 1u));
            g_row_list[r * K_BLOCKS + cnt + pos] = k;
        }
        cnt += __popc(m);
    }
    if (lane == 0) g_row_cnt[r] = cnt;
}

// ---------------- f32 -> (bf16 hi, bf16 lo) split conversion ----------------
__device__ __forceinline__ void split1(float v, __nv_bfloat16& h, __nv_bfloat16& l) {
    h = __float2bfloat16(v);
    l = __float2bfloat16(v - __bfloat162float(h));
}

__global__ void convert_x_kernel(const float* __restrict__ src) {
    size_t i = ((size_t)blockIdx.x * blockDim.x + threadIdx.x) * 4;
    if (i >= (size_t)N_DIM * IN_DIM) return;
    float4 v = *(const float4*)(src + i);
    __nv_bfloat16 h[4], l[4];
    split1(v.x, h[0], l[0]); split1(v.y, h[1], l[1]);
    split1(v.z, h[2], l[2]); split1(v.w, h[3], l[3]);
    *(uint2*)(g_xh + i) = *(uint2*)h;
    *(uint2*)(g_xl + i) = *(uint2*)l;
}

__global__ void convert_w_kernel(const float* __restrict__ src) {
    size_t i = ((size_t)blockIdx.x * blockDim.x + threadIdx.x) * 4;
    if (i >= (size_t)K_BLOCKS * BS * BS) return;
    float4 v = *(const float4*)(src + i);
    __nv_bfloat16 h[4], l[4];
    split1(v.x, h[0], l[0]); split1(v.y, h[1], l[1]);
    split1(v.z, h[2], l[2]); split1(v.w, h[3], l[3]);
    *(uint2*)(g_wh + i) = *(uint2*)h;
    *(uint2*)(g_wl + i) = *(uint2*)l;
}

// ---------------- tensor-core main kernel ----------------
#define LDSM4(R0, R1, R2, R3, ADDR)                                            \
    asm volatile("ldmatrix.sync.aligned.m8n8.x4.shared.b16 {%0,%1,%2,%3}, [%4];" \
                 : "=r"(R0), "=r"(R1), "=r"(R2), "=r"(R3) : "r"(ADDR))

#define MMA16816(C, A, B0, B1)                                                  \
    asm volatile("mma.sync.aligned.m16n8k16.row.col.f32.bf16.bf16.f32 "         \
                 "{%0,%1,%2,%3}, {%4,%5,%6,%7}, {%8,%9}, {%0,%1,%2,%3};"        \
                 : "+f"((C)[0]), "+f"((C)[1]), "+f"((C)[2]), "+f"((C)[3])       \
                 : "r"((A)[0]), "r"((A)[1]), "r"((A)[2]), "r"((A)[3]),          \
                   "r"(B0), "r"(B1))

extern __shared__ __nv_bfloat16 smem[];

// grid = (N/TM, NROWBLK), block = 256 (8 warps in 4(m) x 2(n) layout).
// CTA computes y[n0:n0+128, r*64:(r+1)*64].
__global__ __launch_bounds__(256, 2) void bsl_mma_kernel(
    const float* __restrict__ bias,
    const int* __restrict__ col_idx,
    float* __restrict__ y)
{
    __nv_bfloat16* xh_s = smem;                         // [128][72]
    __nv_bfloat16* xl_s = xh_s + TM * SSTRIDE;          // [128][72]
    __nv_bfloat16* wh_s = xl_s + TM * SSTRIDE;          // [64][72]
    __nv_bfloat16* wl_s = wh_s + BS * SSTRIDE;          // [64][72]

    const int r    = blockIdx.y;
    const int n0   = blockIdx.x * TM;
    const int tid  = threadIdx.x;
    const int wid  = tid >> 5;
    const int lane = tid & 31;
    const int wm   = wid & 3;   // warp row (m): 0..3 -> 32 rows each
    const int wn   = wid >> 2;  // warp col (n): 0..1 -> 32 cols each

    const int cnt   = g_row_cnt[r];
    const int* list = g_row_list + r * K_BLOCKS;

    // Accumulators: [m-frag][n-frag][4]; init with bias (depends on out col only).
    float acc[2][4][4];
    #pragma unroll
    for (int fn = 0; fn < 4; fn++) {
        int ncol = r * BS + wn * 32 + fn * 8 + (lane & 3) * 2;
        float b0 = bias[ncol], b1 = bias[ncol + 1];
        #pragma unroll
        for (int fm = 0; fm < 2; fm++) {
            acc[fm][fn][0] = b0; acc[fm][fn][1] = b1;
            acc[fm][fn][2] = b0; acc[fm][fn][3] = b1;
        }
    }

    // ldmatrix per-lane address components (byte offsets, bf16 = 2B).
    const uint32_t s_xh = (uint32_t)__cvta_generic_to_shared(xh_s);
    const uint32_t s_xl = (uint32_t)__cvta_generic_to_shared(xl_s);
    const uint32_t s_wh = (uint32_t)__cvta_generic_to_shared(wh_s);
    const uint32_t s_wl = (uint32_t)__cvta_generic_to_shared(wl_s);

    // A (16x16 tiles): lanes 0-15 -> rows, lanes 16-31 -> rows with col+8.
    const int a_row   = wm * 32 + (lane & 15);
    const int a_col8  = (lane >> 4) * 8;
    const uint32_t a_off = (uint32_t)(a_row * SSTRIDE + a_col8) * 2;

    // B (two n8xk16 tiles per x4): group g = lane/8.
    const int g      = lane >> 3;
    const int gi     = lane & 7;
    const int b_rowo = (g >> 1) * 8 + gi;    // row within the 16-n pair
    const int b_col8 = (g & 1) * 8;
    const uint32_t b_off = (uint32_t)((wn * 32 + b_rowo) * SSTRIDE + b_col8) * 2;

    for (int it = 0; it < cnt; it++) {
        const int k  = list[it];
        const int cb = col_idx[k];

        // ---- stage x tiles [128 x 64] (hi+lo), 1024 uint4 each ----
        const uint4* xhg = (const uint4*)(g_xh + (size_t)n0 * IN_DIM + cb * BS);
        const uint4* xlg = (const uint4*)(g_xl + (size_t)n0 * IN_DIM + cb * BS);
        #pragma unroll
        for (int u = 0; u < 4; u++) {
            int f = tid + u * 256;          // 0..1023
            int row = f >> 3, seg = f & 7;
            size_t go = (size_t)row * (IN_DIM / 8) + seg;
            *(uint4*)(xh_s + row * SSTRIDE + seg * 8) = xhg[go];
            *(uint4*)(xl_s + row * SSTRIDE + seg * 8) = xlg[go];
        }
        // ---- stage w tiles [64 x 64] (hi+lo), 512 uint4 each ----
        const uint4* whg = (const uint4*)(g_wh + (size_t)k * (BS * BS));
        const uint4* wlg = (const uint4*)(g_wl + (size_t)k * (BS * BS));
        #pragma unroll
        for (int u = 0; u < 2; u++) {
            int f = tid + u * 256;          // 0..511
            int row = f >> 3, seg = f & 7;
            *(uint4*)(wh_s + row * SSTRIDE + seg * 8) = whg[f];
            *(uint4*)(wl_s + row * SSTRIDE + seg * 8) = wlg[f];
        }
        __syncthreads();

        // ---- MMA phase: K=64 as 4 chunks of k16; 3 split terms ----
        #pragma unroll
        for (int kk = 0; kk < 4; kk++) {
            uint32_t ah[2][4], al[2][4], bh[4][2], bl[4][2];
            #pragma unroll
            for (int fm = 0; fm < 2; fm++) {
                uint32_t ao = a_off + (uint32_t)(fm * 16 * SSTRIDE * 2) + kk * 32;
                LDSM4(ah[fm][0], ah[fm][1], ah[fm][2], ah[fm][3], s_xh + ao);
                LDSM4(al[fm][0], al[fm][1], al[fm][2], al[fm][3], s_xl + ao);
            }
            #pragma unroll
            for (int j = 0; j < 4; j += 2) {
                uint32_t bo = b_off + (uint32_t)(j * 8 * SSTRIDE * 2) + kk * 32;
                LDSM4(bh[j][0], bh[j][1], bh[j + 1][0], bh[j + 1][1], s_wh + bo);
                LDSM4(bl[j][0], bl[j][1], bl[j + 1][0], bl[j + 1][1], s_wl + bo);
            }
            #pragma unroll
            for (int fm = 0; fm < 2; fm++)
                #pragma unroll
                for (int fn = 0; fn < 4; fn++) {
                    MMA16816(acc[fm][fn], ah[fm], bh[fn][0], bh[fn][1]);  // xh*wh
                    MMA16816(acc[fm][fn], ah[fm], bl[fn][0], bl[fn][1]);  // xh*wl
                    MMA16816(acc[fm][fn], al[fm], bh[fn][0], bh[fn][1]);  // xl*wh
                }
        }
        __syncthreads();
    }

    // ---- store (every element written: handles poison + bias-only rows) ----
    #pragma unroll
    for (int fm = 0; fm < 2; fm++) {
        int mrow = n0 + wm * 32 + fm * 16 + (lane >> 2);
        #pragma unroll
        for (int fn = 0; fn < 4; fn++) {
            int ncol = r * BS + wn * 32 + fn * 8 + (lane & 3) * 2;
            float2 v0 = make_float2(acc[fm][fn][0], acc[fm][fn][1]);
            float2 v1 = make_float2(acc[fm][fn][2], acc[fm][fn][3]);
            *(float2*)(y + (size_t)mrow * OUT_DIM + ncol)       = v0;
            *(float2*)(y + (size_t)(mrow + 8) * OUT_DIM + ncol) = v1;
        }
    }
}

extern "C" void kernel_launch(void* const* d_in, const int* in_sizes, int n_in,
                              void* d_out, int out_size) {
    (void)in_sizes; (void)n_in; (void)out_size;
    const float* x       = (const float*)d_in[0];
    const float* blocks  = (const float*)d_in[1];
    const float* bias    = (const float*)d_in[2];
    const int*   row_idx = (const int*)d_in[3];
    const int*   col_idx = (const int*)d_in[4];
    float*       y       = (float*)d_out;

    // Prologue: binning + precision-split conversion.
    build_rows_kernel<<<NROWBLK, 32>>>(row_idx);
    {
        size_t nx = (size_t)N_DIM * IN_DIM / 4;   // float4s
        convert_x_kernel<<<(unsigned)((nx + 255) / 256), 256>>>(x);
        size_t nw = (size_t)K_BLOCKS * BS * BS / 4;
        convert_w_kernel<<<(unsigned)((nw + 255) / 256), 256>>>(blocks);
    }

    const int smem_bytes = (2 * TM + 2 * BS) * SSTRIDE * sizeof(__nv_bfloat16);  // 55296
    cudaFuncSetAttribute(bsl_mma_kernel,
                         cudaFuncAttributeMaxDynamicSharedMemorySize, smem_bytes);

    dim3 grid(N_DIM / TM, NROWBLK);
    bsl_mma_kernel<<<grid, 256, smem_bytes>>>(bias, col_idx, y);
}

// round 4
// speedup vs baseline: 4.4504x; 1.2098x over previous
#include <cuda_runtime.h>
#include <cuda_bf16.h>
#include <cstdint>

// Problem constants (fixed shapes per reference)
#define K_BLOCKS 1024
#define NROWBLK  64      // OUT / BS
#define BS       64
#define TM       128     // N-rows per CTA tile
#define IN_DIM   4096
#define OUT_DIM  4096
#define N_DIM    4096

// Per-stage smem layout (bytes). Rows are exactly 128B -> SW128 XOR swizzle.
#define OFF_XH   0
#define OFF_XL   16384
#define OFF_WH   32768
#define OFF_WL   40960
#define STAGE_BYTES 49152   // 48 KB
#define SMEM_TOTAL  (2 * STAGE_BYTES)  // 96 KB -> 2 CTAs/SM

// ---------------- scratch (__device__ globals; no allocs allowed) ----------------
__device__ int g_row_cnt[NROWBLK];
__device__ int g_row_list[NROWBLK * K_BLOCKS];
__device__ __nv_bfloat16 g_xh[(size_t)N_DIM * IN_DIM];
__device__ __nv_bfloat16 g_xl[(size_t)N_DIM * IN_DIM];
__device__ __nv_bfloat16 g_wh[(size_t)K_BLOCKS * BS * BS];
__device__ __nv_bfloat16 g_wl[(size_t)K_BLOCKS * BS * BS];

// ---------------- row binning (one warp per output block-row) ----------------
__global__ void build_rows_kernel(const int* __restrict__ row_idx) {
    int r = blockIdx.x;
    int lane = threadIdx.x;
    int cnt = 0;
    for (int base = 0; base < K_BLOCKS; base += 32) {
        int k = base + lane;
        int v = row_idx[k];
        unsigned m = __ballot_sync(0xffffffffu, v == r);
        if (v == r) {
            int pos = __popc(m & ((1u << lane) - 1u));
            g_row_list[r * K_BLOCKS + cnt + pos] = k;
        }
        cnt += __popc(m);
    }
    if (lane == 0) g_row_cnt[r] = cnt;
}

// ---------------- f32 -> (bf16 hi, bf16 lo) split conversion ----------------
__device__ __forceinline__ void split1(float v, __nv_bfloat16& h, __nv_bfloat16& l) {
    h = __float2bfloat16(v);
    l = __float2bfloat16(v - __bfloat162float(h));
}

__global__ void convert_x_kernel(const float* __restrict__ src) {
    size_t i = ((size_t)blockIdx.x * blockDim.x + threadIdx.x) * 4;
    if (i >= (size_t)N_DIM * IN_DIM) return;
    float4 v = *(const float4*)(src + i);
    __nv_bfloat16 h[4], l[4];
    split1(v.x, h[0], l[0]); split1(v.y, h[1], l[1]);
    split1(v.z, h[2], l[2]); split1(v.w, h[3], l[3]);
    *(uint2*)(g_xh + i) = *(uint2*)h;
    *(uint2*)(g_xl + i) = *(uint2*)l;
}

__global__ void convert_w_kernel(const float* __restrict__ src) {
    size_t i = ((size_t)blockIdx.x * blockDim.x + threadIdx.x) * 4;
    if (i >= (size_t)K_BLOCKS * BS * BS) return;
    float4 v = *(const float4*)(src + i);
    __nv_bfloat16 h[4], l[4];
    split1(v.x, h[0], l[0]); split1(v.y, h[1], l[1]);
    split1(v.z, h[2], l[2]); split1(v.w, h[3], l[3]);
    *(uint2*)(g_wh + i) = *(uint2*)h;
    *(uint2*)(g_wl + i) = *(uint2*)l;
}

// ---------------- PTX helpers ----------------
__device__ __forceinline__ void cp16(uint32_t saddr, const void* gptr) {
    asm volatile("cp.async.cg.shared.global [%0], [%1], 16;\n"
                 :: "r"(saddr), "l"(gptr));
}
#define CP_COMMIT() asm volatile("cp.async.commit_group;\n" ::: "memory")
#define CP_WAIT(n)  asm volatile("cp.async.wait_group %0;\n" :: "n"(n) : "memory")

#define LDSM4(R0, R1, R2, R3, ADDR)                                              \
    asm volatile("ldmatrix.sync.aligned.m8n8.x4.shared.b16 {%0,%1,%2,%3}, [%4];" \
                 : "=r"(R0), "=r"(R1), "=r"(R2), "=r"(R3) : "r"(ADDR))

#define MMA16816(C, A, B0, B1)                                                  \
    asm volatile("mma.sync.aligned.m16n8k16.row.col.f32.bf16.bf16.f32 "         \
                 "{%0,%1,%2,%3}, {%4,%5,%6,%7}, {%8,%9}, {%0,%1,%2,%3};"        \
                 : "+f"((C)[0]), "+f"((C)[1]), "+f"((C)[2]), "+f"((C)[3])       \
                 : "r"((A)[0]), "r"((A)[1]), "r"((A)[2]), "r"((A)[3]),          \
                   "r"(B0), "r"(B1))

extern __shared__ __align__(1024) char smem_raw[];

// grid = (N/TM, NROWBLK), block = 256 (8 warps: 4(m) x 2(n)).
__global__ __launch_bounds__(256, 2) void bsl_mma_kernel(
    const float* __restrict__ bias,
    const int* __restrict__ col_idx,
    float* __restrict__ y)
{
    const int r    = blockIdx.y;
    const int n0   = blockIdx.x * TM;
    const int tid  = threadIdx.x;
    const int wid  = tid >> 5;
    const int lane = tid & 31;
    const int wm   = wid & 3;   // warp row (m): 32 rows each
    const int wn   = wid >> 2;  // warp col (n): 32 cols each

    const int cnt   = g_row_cnt[r];
    const int* list = g_row_list + r * K_BLOCKS;

    const uint32_t smem_u32 = (uint32_t)__cvta_generic_to_shared(smem_raw);

    // ---- accumulators: init with bias (depends only on output column) ----
    float acc[2][4][4];
    #pragma unroll
    for (int fn = 0; fn < 4; fn++) {
        int ncol = r * BS + wn * 32 + fn * 8 + (lane & 3) * 2;
        float b0 = bias[ncol], b1 = bias[ncol + 1];
        #pragma unroll
        for (int fm = 0; fm < 2; fm++) {
            acc[fm][fn][0] = b0; acc[fm][fn][1] = b1;
            acc[fm][fn][2] = b0; acc[fm][fn][3] = b1;
        }
    }

    // ---- per-lane cp.async (store-side) precomputed offsets ----
    // x buffer: 1024 16B chunks (128 rows x 8 chunks), 4 per thread.
    // w buffer:  512 16B chunks ( 64 rows x 8 chunks), 2 per thread.
    uint32_t x_sm_off[4], w_sm_off[2];
    int x_row[4], x_c[4], w_row[2], w_c[2];
    #pragma unroll
    for (int u = 0; u < 4; u++) {
        int f = tid + u * 256;
        x_row[u] = f >> 3; x_c[u] = f & 7;
        x_sm_off[u] = (uint32_t)(x_row[u] * 128 + ((x_c[u] ^ (x_row[u] & 7)) << 4));
    }
    #pragma unroll
    for (int u = 0; u < 2; u++) {
        int f = tid + u * 256;
        w_row[u] = f >> 3; w_c[u] = f & 7;
        w_sm_off[u] = (uint32_t)(w_row[u] * 128 + ((w_c[u] ^ (w_row[u] & 7)) << 4));
    }

    // ---- per-lane ldmatrix (read-side) components ----
    // Both A and B rows have (row & 7) == (lane & 7); chunk = kk*2 + hibit.
    const int m7   = lane & 7;
    const int a_hi = lane >> 4;                       // A col-half
    const int rA0  = wm * 32 + (lane & 15);           // fm=0 row; fm=1 adds 16
    const int g    = lane >> 3;
    const int b_hi = g & 1;                           // B col-half
    const int rB0  = wn * 32 + (g >> 1) * 8 + m7;     // j2 adds 16 per step

    // issue all 12 LDGSTS for one iteration into stage `st`
    auto issue_stage = [&](int st, int k) {
        const int cb = col_idx[k];
        const uint32_t sb = smem_u32 + (uint32_t)st * STAGE_BYTES;
        const char* xh_g = (const char*)(g_xh + (size_t)n0 * IN_DIM + cb * BS);
        const char* xl_g = (const char*)(g_xl + (size_t)n0 * IN_DIM + cb * BS);
        const char* wh_g = (const char*)(g_wh + (size_t)k * (BS * BS));
        const char* wl_g = (const char*)(g_wl + (size_t)k * (BS * BS));
        #pragma unroll
        for (int u = 0; u < 4; u++) {
            size_t go = (size_t)x_row[u] * (IN_DIM * 2) + x_c[u] * 16;
            cp16(sb + OFF_XH + x_sm_off[u], xh_g + go);
            cp16(sb + OFF_XL + x_sm_off[u], xl_g + go);
        }
        #pragma unroll
        for (int u = 0; u < 2; u++) {
            size_t go = (size_t)w_row[u] * 128 + w_c[u] * 16;
            cp16(sb + OFF_WH + w_sm_off[u], wh_g + go);
            cp16(sb + OFF_WL + w_sm_off[u], wl_g + go);
        }
    };

    if (cnt > 0) { issue_stage(0, list[0]); CP_COMMIT(); }

    for (int it = 0; it < cnt; it++) {
        if (it + 1 < cnt) {
            issue_stage((it + 1) & 1, list[it + 1]);
            CP_COMMIT();
            CP_WAIT(1);
        } else {
            CP_WAIT(0);
        }
        __syncthreads();

        const uint32_t sb  = smem_u32 + (uint32_t)(it & 1) * STAGE_BYTES;
        const uint32_t sxh = sb + OFF_XH, sxl = sb + OFF_XL;
        const uint32_t swh = sb + OFF_WH, swl = sb + OFF_WL;

        #pragma unroll
        for (int kk = 0; kk < 4; kk++) {
            uint32_t ah[2][4], al[2][4], bh[4][2], bl[4][2];
            const uint32_t aswz = (uint32_t)((((kk << 1) | a_hi) ^ m7) << 4);
            const uint32_t bswz = (uint32_t)((((kk << 1) | b_hi) ^ m7) << 4);
            #pragma unroll
            for (int fm = 0; fm < 2; fm++) {
                uint32_t ao = (uint32_t)((rA0 + fm * 16) * 128) + aswz;
                LDSM4(ah[fm][0], ah[fm][1], ah[fm][2], ah[fm][3], sxh + ao);
                LDSM4(al[fm][0], al[fm][1], al[fm][2], al[fm][3], sxl + ao);
            }
            #pragma unroll
            for (int j = 0; j < 4; j += 2) {
                uint32_t bo = (uint32_t)((rB0 + j * 8) * 128) + bswz;
                LDSM4(bh[j][0], bh[j][1], bh[j + 1][0], bh[j + 1][1], swh + bo);
                LDSM4(bl[j][0], bl[j][1], bl[j + 1][0], bl[j + 1][1], swl + bo);
            }
            #pragma unroll
            for (int fm = 0; fm < 2; fm++)
                #pragma unroll
                for (int fn = 0; fn < 4; fn++) {
                    MMA16816(acc[fm][fn], ah[fm], bh[fn][0], bh[fn][1]);  // xh*wh
                    MMA16816(acc[fm][fn], ah[fm], bl[fn][0], bl[fn][1]);  // xh*wl
                    MMA16816(acc[fm][fn], al[fm], bh[fn][0], bh[fn][1]);  // xl*wh
                }
        }
        __syncthreads();   // protect stage (it&1) before it is re-filled at it+1
    }

    // ---- store (every element written: handles poison + bias-only rows) ----
    #pragma unroll
    for (int fm = 0; fm < 2; fm++) {
        int mrow = n0 + wm * 32 + fm * 16 + (lane >> 2);
        #pragma unroll
        for (int fn = 0; fn < 4; fn++) {
            int ncol = r * BS + wn * 32 + fn * 8 + (lane & 3) * 2;
            float2 v0 = make_float2(acc[fm][fn][0], acc[fm][fn][1]);
            float2 v1 = make_float2(acc[fm][fn][2], acc[fm][fn][3]);
            *(float2*)(y + (size_t)mrow * OUT_DIM + ncol)       = v0;
            *(float2*)(y + (size_t)(mrow + 8) * OUT_DIM + ncol) = v1;
        }
    }
}

extern "C" void kernel_launch(void* const* d_in, const int* in_sizes, int n_in,
                              void* d_out, int out_size) {
    (void)in_sizes; (void)n_in; (void)out_size;
    const float* x       = (const float*)d_in[0];
    const float* blocks  = (const float*)d_in[1];
    const float* bias    = (const float*)d_in[2];
    const int*   row_idx = (const int*)d_in[3];
    const int*   col_idx = (const int*)d_in[4];
    float*       y       = (float*)d_out;

    build_rows_kernel<<<NROWBLK, 32>>>(row_idx);
    {
        size_t nx = (size_t)N_DIM * IN_DIM / 4;
        convert_x_kernel<<<(unsigned)((nx + 255) / 256), 256>>>(x);
        size_t nw = (size_t)K_BLOCKS * BS * BS / 4;
        convert_w_kernel<<<(unsigned)((nw + 255) / 256), 256>>>(blocks);
    }

    cudaFuncSetAttribute(bsl_mma_kernel,
                         cudaFuncAttributeMaxDynamicSharedMemorySize, SMEM_TOTAL);

    dim3 grid(N_DIM / TM, NROWBLK);
    bsl_mma_kernel<<<grid, 256, SMEM_TOTAL>>>(bias, col_idx, y);
}

// round 7
// speedup vs baseline: 6.0057x; 1.3495x over previous
#include <cuda_runtime.h>
#include <cuda_fp16.h>
#include <cstdint>

// Problem constants (fixed shapes per reference)
#define K_BLOCKS 1024
#define NROWBLK  64      // OUT / BS
#define BS       64
#define TM       128     // N-rows per CTA tile
#define IN_DIM   4096
#define OUT_DIM  4096
#define N_DIM    4096

// Per-stage smem layout (bytes). Rows are exactly 128B -> SW128 XOR swizzle.
#define OFF_XH   0
#define OFF_XL   16384
#define OFF_WH   32768
#define STAGE_BYTES 40960            // 40 KB
#define SMEM_TOTAL  (2 * STAGE_BYTES)  // 80 KB -> 2 CTAs/SM

// ---------------- scratch (__device__ globals; no allocs allowed) ----------------
__device__ int g_row_cnt[NROWBLK];
__device__ int g_row_list[NROWBLK * K_BLOCKS];
__device__ __half g_xh[(size_t)N_DIM * IN_DIM];
__device__ __half g_xl[(size_t)N_DIM * IN_DIM];
__device__ __half g_wh[(size_t)K_BLOCKS * BS * BS];

// ---------------- row binning (one warp per output block-row) ----------------
__global__ void build_rows_kernel(const int* __restrict__ row_idx) {
    int r = blockIdx.x;
    int lane = threadIdx.x;
    int cnt = 0;
    for (int base = 0; base < K_BLOCKS; base += 32) {
        int k = base + lane;
        int v = row_idx[k];
        unsigned m = __ballot_sync(0xffffffffu, v == r);
        if (v == r) {
            int pos = __popc(m & ((1u << lane) - 1u));
            g_row_list[r * K_BLOCKS + cnt + pos] = k;
        }
        cnt += __popc(m);
    }
    if (lane == 0) g_row_cnt[r] = cnt;
}

// ---------------- conversions ----------------
// x: fp16 hi/lo split (hi+lo reproduces f32 to ~2^-22)
__global__ void convert_x_kernel(const float* __restrict__ src) {
    size_t i = ((size_t)blockIdx.x * blockDim.x + threadIdx.x) * 4;
    if (i >= (size_t)N_DIM * IN_DIM) return;
    float4 v = *(const float4*)(src + i);
    __half h[4], l[4];
    float f[4] = {v.x, v.y, v.z, v.w};
    #pragma unroll
    for (int j = 0; j < 4; j++) {
        h[j] = __float2half(f[j]);
        l[j] = __float2half(f[j] - __half2float(h[j]));
    }
    *(uint2*)(g_xh + i) = *(uint2*)h;
    *(uint2*)(g_xl + i) = *(uint2*)l;
}
// w: single fp16 (error 2^-12 avg relative -> aggregate ~1e-4, under 1e-3)
__global__ void convert_w_kernel(const float* __restrict__ src) {
    size_t i = ((size_t)blockIdx.x * blockDim.x + threadIdx.x) * 4;
    if (i >= (size_t)K_BLOCKS * BS * BS) return;
    float4 v = *(const float4*)(src + i);
    __half h[4];
    h[0] = __float2half(v.x); h[1] = __float2half(v.y);
    h[2] = __float2half(v.z); h[3] = __float2half(v.w);
    *(uint2*)(g_wh + i) = *(uint2*)h;
}

// ---------------- PTX helpers ----------------
__device__ __forceinline__ void cp16(uint32_t saddr, const void* gptr) {
    asm volatile("cp.async.cg.shared.global [%0], [%1], 16;\n"
                 :: "r"(saddr), "l"(gptr));
}
#define CP_COMMIT() asm volatile("cp.async.commit_group;\n" ::: "memory")
#define CP_WAIT(n)  asm volatile("cp.async.wait_group %0;\n" :: "n"(n) : "memory")

#define LDSM4(R0, R1, R2, R3, ADDR)                                              \
    asm volatile("ldmatrix.sync.aligned.m8n8.x4.shared.b16 {%0,%1,%2,%3}, [%4];" \
                 : "=r"(R0), "=r"(R1), "=r"(R2), "=r"(R3) : "r"(ADDR))

#define MMA16816(C, A, B0, B1)                                                  \
    asm volatile("mma.sync.aligned.m16n8k16.row.col.f32.f16.f16.f32 "           \
                 "{%0,%1,%2,%3}, {%4,%5,%6,%7}, {%8,%9}, {%0,%1,%2,%3};"        \
                 : "+f"((C)[0]), "+f"((C)[1]), "+f"((C)[2]), "+f"((C)[3])       \
                 : "r"((A)[0]), "r"((A)[1]), "r"((A)[2]), "r"((A)[3]),          \
                   "r"(B0), "r"(B1))

extern __shared__ __align__(1024) char smem_raw[];

// grid = (N/TM, NROWBLK), block = 256 (8 warps: 4(m) x 2(n)).
__global__ __launch_bounds__(256, 2) void bsl_mma_kernel(
    const float* __restrict__ bias,
    const int* __restrict__ col_idx,
    float* __restrict__ y)
{
    const int r    = blockIdx.y;
    const int n0   = blockIdx.x * TM;
    const int tid  = threadIdx.x;
    const int wid  = tid >> 5;
    const int lane = tid & 31;
    const int wm   = wid & 3;   // warp row (m): 32 rows each
    const int wn   = wid >> 2;  // warp col (n): 32 cols each

    const int cnt   = g_row_cnt[r];
    const int* list = g_row_list + r * K_BLOCKS;

    const uint32_t smem_u32 = (uint32_t)__cvta_generic_to_shared(smem_raw);

    // ---- accumulators: init with bias (depends only on output column) ----
    float acc[2][4][4];
    #pragma unroll
    for (int fn = 0; fn < 4; fn++) {
        int ncol = r * BS + wn * 32 + fn * 8 + (lane & 3) * 2;
        float b0 = bias[ncol], b1 = bias[ncol + 1];
        #pragma unroll
        for (int fm = 0; fm < 2; fm++) {
            acc[fm][fn][0] = b0; acc[fm][fn][1] = b1;
            acc[fm][fn][2] = b0; acc[fm][fn][3] = b1;
        }
    }

    // ---- per-lane cp.async (store-side) offsets; SW128 swizzle, 128B rows ----
    // x buffer: 1024 16B chunks (128 rows x 8), 4 per thread.
    // w buffer:  512 16B chunks ( 64 rows x 8), 2 per thread.
    uint32_t x_sm_off[4], w_sm_off[2];
    int x_row[4], x_c[4], w_row[2], w_c[2];
    #pragma unroll
    for (int u = 0; u < 4; u++) {
        int f = tid + u * 256;
        x_row[u] = f >> 3; x_c[u] = f & 7;
        x_sm_off[u] = (uint32_t)(x_row[u] * 128 + ((x_c[u] ^ (x_row[u] & 7)) << 4));
    }
    #pragma unroll
    for (int u = 0; u < 2; u++) {
        int f = tid + u * 256;
        w_row[u] = f >> 3; w_c[u] = f & 7;
        w_sm_off[u] = (uint32_t)(w_row[u] * 128 + ((w_c[u] ^ (w_row[u] & 7)) << 4));
    }

    // ---- per-lane ldmatrix (read-side) components ----
    const int m7   = lane & 7;
    const int a_hi = lane >> 4;                       // A col-half
    const int rA0  = wm * 32 + (lane & 15);           // fm=0 row; fm=1 adds 16
    const int g    = lane >> 3;
    const int b_hi = g & 1;                           // B col-half
    const int rB0  = wn * 32 + (g >> 1) * 8 + m7;

    // issue the 10 LDGSTS for one iteration into stage `st`
    auto issue_stage = [&](int st, int k) {
        const int cb = col_idx[k];
        const uint32_t sb = smem_u32 + (uint32_t)st * STAGE_BYTES;
        const char* xh_g = (const char*)(g_xh + (size_t)n0 * IN_DIM + cb * BS);
        const char* xl_g = (const char*)(g_xl + (size_t)n0 * IN_DIM + cb * BS);
        const char* wh_g = (const char*)(g_wh + (size_t)k * (BS * BS));
        #pragma unroll
        for (int u = 0; u < 4; u++) {
            size_t go = (size_t)x_row[u] * (IN_DIM * 2) + x_c[u] * 16;
            cp16(sb + OFF_XH + x_sm_off[u], xh_g + go);
            cp16(sb + OFF_XL + x_sm_off[u], xl_g + go);
        }
        #pragma unroll
        for (int u = 0; u < 2; u++) {
            size_t go = (size_t)w_row[u] * 128 + w_c[u] * 16;
            cp16(sb + OFF_WH + w_sm_off[u], wh_g + go);
        }
    };

    if (cnt > 0) { issue_stage(0, list[0]); CP_COMMIT(); }

    for (int it = 0; it < cnt; it++) {
        if (it + 1 < cnt) {
            issue_stage((it + 1) & 1, list[it + 1]);
            CP_COMMIT();
            CP_WAIT(1);
        } else {
            CP_WAIT(0);
        }
        __syncthreads();

        const uint32_t sb  = smem_u32 + (uint32_t)(it & 1) * STAGE_BYTES;
        const uint32_t sxh = sb + OFF_XH, sxl = sb + OFF_XL;
        const uint32_t swh = sb + OFF_WH;

        #pragma unroll
        for (int kk = 0; kk < 4; kk++) {
            uint32_t ah[2][4], al[2][4], bh[4][2];
            const uint32_t aswz = (uint32_t)((((kk << 1) | a_hi) ^ m7) << 4);
            const uint32_t bswz = (uint32_t)((((kk << 1) | b_hi) ^ m7) << 4);
            #pragma unroll
            for (int fm = 0; fm < 2; fm++) {
                uint32_t ao = (uint32_t)((rA0 + fm * 16) * 128) + aswz;
                LDSM4(ah[fm][0], ah[fm][1], ah[fm][2], ah[fm][3], sxh + ao);
                LDSM4(al[fm][0], al[fm][1], al[fm][2], al[fm][3], sxl + ao);
            }
            #pragma unroll
            for (int j = 0; j < 4; j += 2) {
                uint32_t bo = (uint32_t)((rB0 + j * 8) * 128) + bswz;
                LDSM4(bh[j][0], bh[j][1], bh[j + 1][0], bh[j + 1][1], swh + bo);
            }
            #pragma unroll
            for (int fm = 0; fm < 2; fm++)
                #pragma unroll
                for (int fn = 0; fn < 4; fn++) {
                    MMA16816(acc[fm][fn], ah[fm], bh[fn][0], bh[fn][1]);  // xh*wh
                    MMA16816(acc[fm][fn], al[fm], bh[fn][0], bh[fn][1]);  // xl*wh
                }
        }
        __syncthreads();   // protect stage (it&1) before refill at it+1
    }

    // ---- store (every element written: handles poison + bias-only rows) ----
    #pragma unroll
    for (int fm = 0; fm < 2; fm++) {
        int mrow = n0 + wm * 32 + fm * 16 + (lane >> 2);
        #pragma unroll
        for (int fn = 0; fn < 4; fn++) {
            int ncol = r * BS + wn * 32 + fn * 8 + (lane & 3) * 2;
            float2 v0 = make_float2(acc[fm][fn][0], acc[fm][fn][1]);
            float2 v1 = make_float2(acc[fm][fn][2], acc[fm][fn][3]);
            *(float2*)(y + (size_t)mrow * OUT_DIM + ncol)       = v0;
            *(float2*)(y + (size_t)(mrow + 8) * OUT_DIM + ncol) = v1;
        }
    }
}

extern "C" void kernel_launch(void* const* d_in, const int* in_sizes, int n_in,
                              void* d_out, int out_size) {
    (void)in_sizes; (void)n_in; (void)out_size;
    const float* x       = (const float*)d_in[0];
    const float* blocks  = (const float*)d_in[1];
    const float* bias    = (const float*)d_in[2];
    const int*   row_idx = (const int*)d_in[3];
    const int*   col_idx = (const int*)d_in[4];
    float*       y       = (float*)d_out;

    build_rows_kernel<<<NROWBLK, 32>>>(row_idx);
    {
        size_t nx = (size_t)N_DIM * IN_DIM / 4;
        convert_x_kernel<<<(unsigned)((nx + 255) / 256), 256>>>(x);
        size_t nw = (size_t)K_BLOCKS * BS * BS / 4;
        convert_w_kernel<<<(unsigned)((nw + 255) / 256), 256>>>(blocks);
    }

    cudaFuncSetAttribute(bsl_mma_kernel,
                         cudaFuncAttributeMaxDynamicSharedMemorySize, SMEM_TOTAL);

    dim3 grid(N_DIM / TM, NROWBLK);
    bsl_mma_kernel<<<grid, 256, SMEM_TOTAL>>>(bias, col_idx, y);
}

// round 8
// speedup vs baseline: 8.7207x; 1.4521x over previous
#include <cuda_runtime.h>
#include <cuda_fp16.h>
#include <cstdint>

// Problem constants (fixed shapes per reference)
#define K_BLOCKS 1024
#define NROWBLK  64      // OUT / BS
#define BS       64
#define TM       128     // N-rows per CTA tile
#define IN_DIM   4096
#define OUT_DIM  4096
#define N_DIM    4096

// Per-stage smem layout (bytes). Rows are exactly 128B -> SW128 XOR swizzle.
#define OFF_X    0
#define OFF_W    16384
#define STAGE_BYTES 24576            // 24 KB
#define NSTAGE   4
#define SMEM_TOTAL  (NSTAGE * STAGE_BYTES)  // 96 KB -> 2 CTAs/SM

// ---------------- scratch (__device__ globals; no allocs allowed) ----------------
__device__ int g_row_cnt[NROWBLK];
__device__ int g_row_list[NROWBLK * K_BLOCKS];
__device__ __half g_x16[(size_t)N_DIM * IN_DIM];
__device__ __half g_w16[(size_t)K_BLOCKS * BS * BS];

// ---------------- row binning (one warp per output block-row) ----------------
__global__ void build_rows_kernel(const int* __restrict__ row_idx) {
    int r = blockIdx.x;
    int lane = threadIdx.x;
    int cnt = 0;
    for (int base = 0; base < K_BLOCKS; base += 32) {
        int k = base + lane;
        int v = row_idx[k];
        unsigned m = __ballot_sync(0xffffffffu, v == r);
        if (v == r) {
            int pos = __popc(m & ((1u << lane) - 1u));
            g_row_list[r * K_BLOCKS + cnt + pos] = k;
        }
        cnt += __popc(m);
    }
    if (lane == 0) g_row_cnt[r] = cnt;
}

// ---------------- f32 -> fp16 conversions ----------------
__global__ void convert_x_kernel(const float* __restrict__ src) {
    size_t i = ((size_t)blockIdx.x * blockDim.x + threadIdx.x) * 4;
    if (i >= (size_t)N_DIM * IN_DIM) return;
    float4 v = *(const float4*)(src + i);
    __half h[4];
    h[0] = __float2half(v.x); h[1] = __float2half(v.y);
    h[2] = __float2half(v.z); h[3] = __float2half(v.w);
    *(uint2*)(g_x16 + i) = *(uint2*)h;
}
__global__ void convert_w_kernel(const float* __restrict__ src) {
    size_t i = ((size_t)blockIdx.x * blockDim.x + threadIdx.x) * 4;
    if (i >= (size_t)K_BLOCKS * BS * BS) return;
    float4 v = *(const float4*)(src + i);
    __half h[4];
    h[0] = __float2half(v.x); h[1] = __float2half(v.y);
    h[2] = __float2half(v.z); h[3] = __float2half(v.w);
    *(uint2*)(g_w16 + i) = *(uint2*)h;
}

// ---------------- PTX helpers ----------------
__device__ __forceinline__ void cp16(uint32_t saddr, const void* gptr) {
    asm volatile("cp.async.cg.shared.global [%0], [%1], 16;\n"
                 :: "r"(saddr), "l"(gptr));
}
#define CP_COMMIT() asm volatile("cp.async.commit_group;\n" ::: "memory")
#define CP_WAIT(n)  asm volatile("cp.async.wait_group %0;\n" :: "n"(n) : "memory")

#define LDSM4(R0, R1, R2, R3, ADDR)                                              \
    asm volatile("ldmatrix.sync.aligned.m8n8.x4.shared.b16 {%0,%1,%2,%3}, [%4];" \
                 : "=r"(R0), "=r"(R1), "=r"(R2), "=r"(R3) : "r"(ADDR))

#define MMA16816(C, A, B0, B1)                                                  \
    asm volatile("mma.sync.aligned.m16n8k16.row.col.f32.f16.f16.f32 "           \
                 "{%0,%1,%2,%3}, {%4,%5,%6,%7}, {%8,%9}, {%0,%1,%2,%3};"        \
                 : "+f"((C)[0]), "+f"((C)[1]), "+f"((C)[2]), "+f"((C)[3])       \
                 : "r"((A)[0]), "r"((A)[1]), "r"((A)[2]), "r"((A)[3]),          \
                   "r"(B0), "r"(B1))

extern __shared__ __align__(1024) char smem_raw[];

// grid = (N/TM, NROWBLK), block = 256 (8 warps: 4(m) x 2(n)).
__global__ __launch_bounds__(256, 2) void bsl_mma_kernel(
    const float* __restrict__ bias,
    const int* __restrict__ col_idx,
    float* __restrict__ y)
{
    const int r    = blockIdx.y;
    const int n0   = blockIdx.x * TM;
    const int tid  = threadIdx.x;
    const int wid  = tid >> 5;
    const int lane = tid & 31;
    const int wm   = wid & 3;   // warp row (m): 32 rows each
    const int wn   = wid >> 2;  // warp col (n): 32 cols each

    const int cnt   = g_row_cnt[r];
    const int* list = g_row_list + r * K_BLOCKS;

    const uint32_t smem_u32 = (uint32_t)__cvta_generic_to_shared(smem_raw);

    // ---- accumulators: init with bias (depends only on output column) ----
    float acc[2][4][4];
    #pragma unroll
    for (int fn = 0; fn < 4; fn++) {
        int ncol = r * BS + wn * 32 + fn * 8 + (lane & 3) * 2;
        float b0 = bias[ncol], b1 = bias[ncol + 1];
        #pragma unroll
        for (int fm = 0; fm < 2; fm++) {
            acc[fm][fn][0] = b0; acc[fm][fn][1] = b1;
            acc[fm][fn][2] = b0; acc[fm][fn][3] = b1;
        }
    }

    // ---- per-lane cp.async (store-side) offsets; SW128 swizzle, 128B rows ----
    // x buffer: 1024 16B chunks (128 rows x 8), 4 per thread.
    // w buffer:  512 16B chunks ( 64 rows x 8), 2 per thread.
    uint32_t x_sm_off[4], w_sm_off[2];
    int x_row[4], x_c[4], w_row[2], w_c[2];
    #pragma unroll
    for (int u = 0; u < 4; u++) {
        int f = tid + u * 256;
        x_row[u] = f >> 3; x_c[u] = f & 7;
        x_sm_off[u] = (uint32_t)(x_row[u] * 128 + ((x_c[u] ^ (x_row[u] & 7)) << 4));
    }
    #pragma unroll
    for (int u = 0; u < 2; u++) {
        int f = tid + u * 256;
        w_row[u] = f >> 3; w_c[u] = f & 7;
        w_sm_off[u] = (uint32_t)(w_row[u] * 128 + ((w_c[u] ^ (w_row[u] & 7)) << 4));
    }

    // ---- per-lane ldmatrix (read-side) components ----
    const int m7   = lane & 7;
    const int a_hi = lane >> 4;                       // A col-half
    const int rA0  = wm * 32 + (lane & 15);           // fm=0 row; fm=1 adds 16
    const int g    = lane >> 3;
    const int b_hi = g & 1;                           // B col-half
    const int rB0  = wn * 32 + (g >> 1) * 8 + m7;

    // issue the 6 LDGSTS for one block into stage `st`
    auto issue_stage = [&](int st, int k) {
        const int cb = col_idx[k];
        const uint32_t sb = smem_u32 + (uint32_t)st * STAGE_BYTES;
        const char* x_g = (const char*)(g_x16 + (size_t)n0 * IN_DIM + cb * BS);
        const char* w_g = (const char*)(g_w16 + (size_t)k * (BS * BS));
        #pragma unroll
        for (int u = 0; u < 4; u++) {
            size_t go = (size_t)x_row[u] * (IN_DIM * 2) + x_c[u] * 16;
            cp16(sb + OFF_X + x_sm_off[u], x_g + go);
        }
        #pragma unroll
        for (int u = 0; u < 2; u++) {
            size_t go = (size_t)w_row[u] * 128 + w_c[u] * 16;
            cp16(sb + OFF_W + w_sm_off[u], w_g + go);
        }
    };

    // ---- prologue: fill up to 3 stages ahead ----
    {
        int pre = cnt < 3 ? cnt : 3;
        for (int i = 0; i < pre; i++) { issue_stage(i, list[i]); CP_COMMIT(); }
    }

    for (int it = 0; it < cnt; it++) {
        const int rem = cnt - 1 - it;   // stages still pending after this one
        if (rem >= 3) {
            issue_stage((it + 3) & (NSTAGE - 1), list[it + 3]);
            CP_COMMIT();
            CP_WAIT(3);
        } else if (rem == 2) CP_WAIT(2);
        else if (rem == 1)   CP_WAIT(1);
        else                 CP_WAIT(0);
        __syncthreads();

        const uint32_t sb = smem_u32 + (uint32_t)(it & (NSTAGE - 1)) * STAGE_BYTES;
        const uint32_t sx = sb + OFF_X, sw = sb + OFF_W;

        #pragma unroll
        for (int kk = 0; kk < 4; kk++) {
            uint32_t a[2][4], b[4][2];
            const uint32_t aswz = (uint32_t)((((kk << 1) | a_hi) ^ m7) << 4);
            const uint32_t bswz = (uint32_t)((((kk << 1) | b_hi) ^ m7) << 4);
            #pragma unroll
            for (int fm = 0; fm < 2; fm++) {
                uint32_t ao = (uint32_t)((rA0 + fm * 16) * 128) + aswz;
                LDSM4(a[fm][0], a[fm][1], a[fm][2], a[fm][3], sx + ao);
            }
            #pragma unroll
            for (int j = 0; j < 4; j += 2) {
                uint32_t bo = (uint32_t)((rB0 + j * 8) * 128) + bswz;
                LDSM4(b[j][0], b[j][1], b[j + 1][0], b[j + 1][1], sw + bo);
            }
            #pragma unroll
            for (int fm = 0; fm < 2; fm++)
                #pragma unroll
                for (int fn = 0; fn < 4; fn++)
                    MMA16816(acc[fm][fn], a[fm], b[fn][0], b[fn][1]);
        }
        __syncthreads();   // protect stage (it & 3) before refill at it+3
    }

    // ---- store (every element written: handles poison + bias-only rows) ----
    #pragma unroll
    for (int fm = 0; fm < 2; fm++) {
        int mrow = n0 + wm * 32 + fm * 16 + (lane >> 2);
        #pragma unroll
        for (int fn = 0; fn < 4; fn++) {
            int ncol = r * BS + wn * 32 + fn * 8 + (lane & 3) * 2;
            float2 v0 = make_float2(acc[fm][fn][0], acc[fm][fn][1]);
            float2 v1 = make_float2(acc[fm][fn][2], acc[fm][fn][3]);
            *(float2*)(y + (size_t)mrow * OUT_DIM + ncol)       = v0;
            *(float2*)(y + (size_t)(mrow + 8) * OUT_DIM + ncol) = v1;
        }
    }
}

extern "C" void kernel_launch(void* const* d_in, const int* in_sizes, int n_in,
                              void* d_out, int out_size) {
    (void)in_sizes; (void)n_in; (void)out_size;
    const float* x       = (const float*)d_in[0];
    const float* blocks  = (const float*)d_in[1];
    const float* bias    = (const float*)d_in[2];
    const int*   row_idx = (const int*)d_in[3];
    const int*   col_idx = (const int*)d_in[4];
    float*       y       = (float*)d_out;

    build_rows_kernel<<<NROWBLK, 32>>>(row_idx);
    {
        size_t nx = (size_t)N_DIM * IN_DIM / 4;
        convert_x_kernel<<<(unsigned)((nx + 255) / 256), 256>>>(x);
        size_t nw = (size_t)K_BLOCKS * BS * BS / 4;
        convert_w_kernel<<<(unsigned)((nw + 255) / 256), 256>>>(blocks);
    }

    cudaFuncSetAttribute(bsl_mma_kernel,
                         cudaFuncAttributeMaxDynamicSharedMemorySize, SMEM_TOTAL);

    dim3 grid(N_DIM / TM, NROWBLK);
    bsl_mma_kernel<<<grid, 256, SMEM_TOTAL>>>(bias, col_idx, y);
}

// round 11
// speedup vs baseline: 9.3955x; 1.0774x over previous
#include <cuda_runtime.h>
#include <cuda_fp16.h>
#include <cstdint>

// Problem constants (fixed shapes per reference)
#define K_BLOCKS 1024
#define NROWBLK  64      // OUT / BS
#define BS       64
#define TM       128     // N-rows per CTA tile
#define IN_DIM   4096
#define OUT_DIM  4096
#define N_DIM    4096

// Per-stage smem layout (bytes). Rows are exactly 128B -> SW128 XOR swizzle.
#define OFF_X    0
#define OFF_W    16384
#define STAGE_BYTES 24576            // 24 KB
#define NSTAGE   3
#define SMEM_TOTAL  (NSTAGE * STAGE_BYTES)  // 72 KB -> 3 CTAs/SM

// ---------------- scratch (__device__ globals; no allocs allowed) ----------------
__device__ int g_row_cnt[NROWBLK];
__device__ int g_row_list[NROWBLK * K_BLOCKS];
__device__ __half g_x16[(size_t)N_DIM * IN_DIM];
__device__ __half g_w16[(size_t)K_BLOCKS * BS * BS];

// ---------------- row binning (one warp per output block-row) ----------------
__global__ void build_rows_kernel(const int* __restrict__ row_idx) {
    int r = blockIdx.x;
    int lane = threadIdx.x;
    int cnt = 0;
    for (int base = 0; base < K_BLOCKS; base += 32) {
        int k = base + lane;
        int v = row_idx[k];
        unsigned m = __ballot_sync(0xffffffffu, v == r);
        if (v == r) {
            int pos = __popc(m & ((1u << lane) - 1u));
            g_row_list[r * K_BLOCKS + cnt + pos] = k;
        }
        cnt += __popc(m);
    }
    if (lane == 0) g_row_cnt[r] = cnt;
}

// ---------------- merged f32 -> fp16 conversion (x then w, one launch) ----------------
#define NX4 ((size_t)N_DIM * IN_DIM / 4)                 // float4 groups in x
#define NW4 ((size_t)K_BLOCKS * BS * BS / 4)             // float4 groups in w
__global__ void convert_all_kernel(const float* __restrict__ x,
                                   const float* __restrict__ w) {
    size_t g = (size_t)blockIdx.x * blockDim.x + threadIdx.x;
    const float* src;
    __half* dst;
    size_t i;
    if (g < NX4)            { src = x; dst = g_x16; i = g * 4; }
    else if (g < NX4 + NW4) { src = w; dst = g_w16; i = (g - NX4) * 4; }
    else return;
    float4 v = *(const float4*)(src + i);
    __half h[4];
    h[0] = __float2half(v.x); h[1] = __float2half(v.y);
    h[2] = __float2half(v.z); h[3] = __float2half(v.w);
    *(uint2*)(dst + i) = *(uint2*)h;
}

// ---------------- PTX helpers ----------------
__device__ __forceinline__ void cp16(uint32_t saddr, const void* gptr) {
    asm volatile("cp.async.cg.shared.global [%0], [%1], 16;\n"
                 :: "r"(saddr), "l"(gptr));
}
#define CP_COMMIT() asm volatile("cp.async.commit_group;\n" ::: "memory")
#define CP_WAIT(n)  asm volatile("cp.async.wait_group %0;\n" :: "n"(n) : "memory")

#define LDSM4(R0, R1, R2, R3, ADDR)                                              \
    asm volatile("ldmatrix.sync.aligned.m8n8.x4.shared.b16 {%0,%1,%2,%3}, [%4];" \
                 : "=r"(R0), "=r"(R1), "=r"(R2), "=r"(R3) : "r"(ADDR))

#define MMA16816(C, A, B0, B1)                                                  \
    asm volatile("mma.sync.aligned.m16n8k16.row.col.f32.f16.f16.f32 "           \
                 "{%0,%1,%2,%3}, {%4,%5,%6,%7}, {%8,%9}, {%0,%1,%2,%3};"        \
                 : "+f"((C)[0]), "+f"((C)[1]), "+f"((C)[2]), "+f"((C)[3])       \
                 : "r"((A)[0]), "r"((A)[1]), "r"((A)[2]), "r"((A)[3]),          \
                   "r"(B0), "r"(B1))

extern __shared__ __align__(1024) char smem_raw[];

// grid = (N/TM, NROWBLK), block = 256 (8 warps: 4(m) x 2(n)), 3 CTAs/SM.
__global__ __launch_bounds__(256, 3) void bsl_mma_kernel(
    const float* __restrict__ bias,
    const int* __restrict__ col_idx,
    float* __restrict__ y)
{
    const int r    = blockIdx.y;
    const int n0   = blockIdx.x * TM;
    const int tid  = threadIdx.x;
    const int wid  = tid >> 5;
    const int lane = tid & 31;
    const int wm   = wid & 3;   // warp row (m): 32 rows each
    const int wn   = wid >> 2;  // warp col (n): 32 cols each

    const int cnt   = g_row_cnt[r];
    const int* list = g_row_list + r * K_BLOCKS;

    const uint32_t smem_u32 = (uint32_t)__cvta_generic_to_shared(smem_raw);

    // ---- accumulators: init with bias (depends only on output column) ----
    float acc[2][4][4];
    #pragma unroll
    for (int fn = 0; fn < 4; fn++) {
        int ncol = r * BS + wn * 32 + fn * 8 + (lane & 3) * 2;
        float b0 = bias[ncol], b1 = bias[ncol + 1];
        #pragma unroll
        for (int fm = 0; fm < 2; fm++) {
            acc[fm][fn][0] = b0; acc[fm][fn][1] = b1;
            acc[fm][fn][2] = b0; acc[fm][fn][3] = b1;
        }
    }

    // ---- per-lane cp.async offsets (u32 byte offsets; SW128, 128B rows) ----
    // x: 1024 16B chunks (128 rows x 8), 4/thread. w: 512 chunks, 2/thread.
    uint32_t x_sm_off[4], x_g_off[4], w_sm_off[2], w_g_off[2];
    #pragma unroll
    for (int u = 0; u < 4; u++) {
        int f = tid + u * 256;
        int row = f >> 3, c = f & 7;
        x_sm_off[u] = (uint32_t)(row * 128 + ((c ^ (row & 7)) << 4));
        x_g_off[u]  = (uint32_t)(row * (IN_DIM * 2) + c * 16);
    }
    #pragma unroll
    for (int u = 0; u < 2; u++) {
        int f = tid + u * 256;
        int row = f >> 3, c = f & 7;
        w_sm_off[u] = (uint32_t)(row * 128 + ((c ^ (row & 7)) << 4));
        w_g_off[u]  = (uint32_t)(row * 128 + c * 16);
    }

    // ---- per-lane ldmatrix (read-side) components ----
    const int m7   = lane & 7;
    const int a_hi = lane >> 4;                       // A col-half
    const int rA0  = wm * 32 + (lane & 15);           // fm=0 row; fm=1 adds 16
    const int g    = lane >> 3;
    const int b_hi = g & 1;                           // B col-half
    const int rB0  = wn * 32 + (g >> 1) * 8 + m7;

    const char* x_base = (const char*)(g_x16 + (size_t)n0 * IN_DIM);

    // issue the 6 LDGSTS for one block into stage `st`
    auto issue_stage = [&](int st, int k) {
        const int cb = col_idx[k];
        const uint32_t sb = smem_u32 + (uint32_t)st * STAGE_BYTES;
        const char* x_g = x_base + (uint32_t)cb * (BS * 2);
        const char* w_g = (const char*)g_w16 + (uint32_t)k * (BS * BS * 2);
        #pragma unroll
        for (int u = 0; u < 4; u++)
            cp16(sb + OFF_X + x_sm_off[u], x_g + x_g_off[u]);
        #pragma unroll
        for (int u = 0; u < 2; u++)
            cp16(sb + OFF_W + w_sm_off[u], w_g + w_g_off[u]);
    };

    // ---- prologue: fill 2 stages ahead ----
    {
        int pre = cnt < 2 ? cnt : 2;
        for (int i = 0; i < pre; i++) { issue_stage(i, list[i]); CP_COMMIT(); }
    }

    // stage index cycling (avoid % in loop)
    int st = 0;                         // stage of iter `it`
    int st_next = (NSTAGE > 2) ? 2 : 0; // stage of iter `it+2` (issue slot)

    for (int it = 0; it < cnt; it++) {
        if (it + 1 < cnt) CP_WAIT(1); else CP_WAIT(0);
        __syncthreads();                // publishes stage `it`; also fences
                                        // prior readers of the re-fill slot
        if (it + 2 < cnt) {
            issue_stage(st_next, list[it + 2]);
            CP_COMMIT();
        }

        const uint32_t sb = smem_u32 + (uint32_t)st * STAGE_BYTES;
        const uint32_t sx = sb + OFF_X, sw = sb + OFF_W;

        #pragma unroll
        for (int kk = 0; kk < 4; kk++) {
            uint32_t a[2][4], b[4][2];
            const uint32_t aswz = (uint32_t)((((kk << 1) | a_hi) ^ m7) << 4);
            const uint32_t bswz = (uint32_t)((((kk << 1) | b_hi) ^ m7) << 4);
            #pragma unroll
            for (int fm = 0; fm < 2; fm++) {
                uint32_t ao = (uint32_t)((rA0 + fm * 16) * 128) + aswz;
                LDSM4(a[fm][0], a[fm][1], a[fm][2], a[fm][3], sx + ao);
            }
            #pragma unroll
            for (int j = 0; j < 4; j += 2) {
                uint32_t bo = (uint32_t)((rB0 + j * 8) * 128) + bswz;
                LDSM4(b[j][0], b[j][1], b[j + 1][0], b[j + 1][1], sw + bo);
            }
            #pragma unroll
            for (int fm = 0; fm < 2; fm++)
                #pragma unroll
                for (int fn = 0; fn < 4; fn++)
                    MMA16816(acc[fm][fn], a[fm], b[fn][0], b[fn][1]);
        }

        st      = (st == NSTAGE - 1) ? 0 : st + 1;
        st_next = (st_next == NSTAGE - 1) ? 0 : st_next + 1;
    }

    // ---- store (every element written: handles poison + bias-only rows) ----
    #pragma unroll
    for (int fm = 0; fm < 2; fm++) {
        int mrow = n0 + wm * 32 + fm * 16 + (lane >> 2);
        #pragma unroll
        for (int fn = 0; fn < 4; fn++) {
            int ncol = r * BS + wn * 32 + fn * 8 + (lane & 3) * 2;
            float2 v0 = make_float2(acc[fm][fn][0], acc[fm][fn][1]);
            float2 v1 = make_float2(acc[fm][fn][2], acc[fm][fn][3]);
            *(float2*)(y + (size_t)mrow * OUT_DIM + ncol)       = v0;
            *(float2*)(y + (size_t)(mrow + 8) * OUT_DIM + ncol) = v1;
        }
    }
}

extern "C" void kernel_launch(void* const* d_in, const int* in_sizes, int n_in,
                              void* d_out, int out_size) {
    (void)in_sizes; (void)n_in; (void)out_size;
    const float* x       = (const float*)d_in[0];
    const float* blocks  = (const float*)d_in[1];
    const float* bias    = (const float*)d_in[2];
    const int*   row_idx = (const int*)d_in[3];
    const int*   col_idx = (const int*)d_in[4];
    float*       y       = (float*)d_out;

    build_rows_kernel<<<NROWBLK, 32>>>(row_idx);
    {
        size_t ntot = NX4 + NW4;
        convert_all_kernel<<<(unsigned)((ntot + 255) / 256), 256>>>(x, blocks);
    }

    cudaFuncSetAttribute(bsl_mma_kernel,
                         cudaFuncAttributeMaxDynamicSharedMemorySize, SMEM_TOTAL);

    dim3 grid(N_DIM / TM, NROWBLK);
    bsl_mma_kernel<<<grid, 256, SMEM_TOTAL>>>(bias, col_idx, y);
}

// round 12
// speedup vs baseline: 9.6151x; 1.0234x over previous
#include <cuda_runtime.h>
#include <cuda_fp16.h>
#include <cstdint>

// Problem constants (fixed shapes per reference)
#define K_BLOCKS 1024
#define NROWBLK  64      // OUT / BS
#define BS       64
#define TM       128     // N-rows per CTA tile
#define IN_DIM   4096
#define OUT_DIM  4096
#define N_DIM    4096

// Per-stage smem layout (bytes). Rows are exactly 128B -> SW128 XOR swizzle.
#define OFF_X    0
#define OFF_W    16384
#define STAGE_BYTES 24576            // 24 KB
#define NSTAGE   3
#define SMEM_TOTAL  (NSTAGE * STAGE_BYTES)  // 72 KB -> 3 CTAs/SM

// ---------------- scratch (__device__ globals; no allocs allowed) ----------------
__device__ int g_row_cnt[NROWBLK];
__device__ int g_row_list[NROWBLK * K_BLOCKS];
__device__ __half g_x16[(size_t)N_DIM * IN_DIM];
__device__ __half g_w16[(size_t)K_BLOCKS * BS * BS];

// ---------------- fused setup: binning (blocks 0..63) + f32->fp16 convert ----------------
#define NX4 ((size_t)N_DIM * IN_DIM / 4)                 // float4 groups in x
#define NW4 ((size_t)K_BLOCKS * BS * BS / 4)             // float4 groups in w
#define CONV_BLOCKS ((unsigned)((NX4 + NW4 + 255) / 256))

__global__ void setup_kernel(const float* __restrict__ x,
                             const float* __restrict__ w,
                             const int* __restrict__ row_idx) {
    if (blockIdx.x < NROWBLK) {
        // ---- per-row binning; warp 0 only. Overlaps with conversion blocks. ----
        if (threadIdx.x >= 32) return;
        int r = blockIdx.x;
        int lane = threadIdx.x;
        int cnt = 0;
        for (int base = 0; base < K_BLOCKS; base += 32) {
            int k = base + lane;
            int v = row_idx[k];
            unsigned m = __ballot_sync(0xffffffffu, v == r);
            if (v == r) {
                int pos = __popc(m & ((1u << lane) - 1u));
                g_row_list[r * K_BLOCKS + cnt + pos] = k;
            }
            cnt += __popc(m);
        }
        if (lane == 0) g_row_cnt[r] = cnt;
        return;
    }
    // ---- conversion: x plane then w plane ----
    size_t g = (size_t)(blockIdx.x - NROWBLK) * blockDim.x + threadIdx.x;
    const float* src;
    __half* dst;
    size_t i;
    if (g < NX4)            { src = x; dst = g_x16; i = g * 4; }
    else if (g < NX4 + NW4) { src = w; dst = g_w16; i = (g - NX4) * 4; }
    else return;
    float4 v = *(const float4*)(src + i);
    __half h[4];
    h[0] = __float2half(v.x); h[1] = __float2half(v.y);
    h[2] = __float2half(v.z); h[3] = __float2half(v.w);
    *(uint2*)(dst + i) = *(uint2*)h;
}

// ---------------- PTX helpers ----------------
__device__ __forceinline__ void cp16(uint32_t saddr, const void* gptr) {
    asm volatile("cp.async.cg.shared.global [%0], [%1], 16;\n"
                 :: "r"(saddr), "l"(gptr));
}
#define CP_COMMIT() asm volatile("cp.async.commit_group;\n" ::: "memory")
#define CP_WAIT(n)  asm volatile("cp.async.wait_group %0;\n" :: "n"(n) : "memory")

#define LDSM4(R0, R1, R2, R3, ADDR)                                              \
    asm volatile("ldmatrix.sync.aligned.m8n8.x4.shared.b16 {%0,%1,%2,%3}, [%4];" \
                 : "=r"(R0), "=r"(R1), "=r"(R2), "=r"(R3) : "r"(ADDR))

#define MMA16816(C, A, B0, B1)                                                  \
    asm volatile("mma.sync.aligned.m16n8k16.row.col.f32.f16.f16.f32 "           \
                 "{%0,%1,%2,%3}, {%4,%5,%6,%7}, {%8,%9}, {%0,%1,%2,%3};"        \
                 : "+f"((C)[0]), "+f"((C)[1]), "+f"((C)[2]), "+f"((C)[3])       \
                 : "r"((A)[0]), "r"((A)[1]), "r"((A)[2]), "r"((A)[3]),          \
                   "r"(B0), "r"(B1))

extern __shared__ __align__(1024) char smem_raw[];

// grid = (N/TM, NROWBLK), block = 256 (8 warps: 4(m) x 2(n)), 3 CTAs/SM.
__global__ __launch_bounds__(256, 3) void bsl_mma_kernel(
    const float* __restrict__ bias,
    const int* __restrict__ col_idx,
    float* __restrict__ y)
{
    const int r    = blockIdx.y;
    const int n0   = blockIdx.x * TM;
    const int tid  = threadIdx.x;
    const int wid  = tid >> 5;
    const int lane = tid & 31;
    const int wm   = wid & 3;   // warp row (m): 32 rows each
    const int wn   = wid >> 2;  // warp col (n): 32 cols each

    const int cnt   = g_row_cnt[r];
    const int* list = g_row_list + r * K_BLOCKS;

    const uint32_t smem_u32 = (uint32_t)__cvta_generic_to_shared(smem_raw);

    // ---- accumulators: init with bias (depends only on output column) ----
    float acc[2][4][4];
    #pragma unroll
    for (int fn = 0; fn < 4; fn++) {
        int ncol = r * BS + wn * 32 + fn * 8 + (lane & 3) * 2;
        float b0 = bias[ncol], b1 = bias[ncol + 1];
        #pragma unroll
        for (int fm = 0; fm < 2; fm++) {
            acc[fm][fn][0] = b0; acc[fm][fn][1] = b1;
            acc[fm][fn][2] = b0; acc[fm][fn][3] = b1;
        }
    }

    // ---- per-lane cp.async offsets (u32 byte offsets; SW128, 128B rows) ----
    uint32_t x_sm_off[4], x_g_off[4], w_sm_off[2], w_g_off[2];
    #pragma unroll
    for (int u = 0; u < 4; u++) {
        int f = tid + u * 256;
        int row = f >> 3, c = f & 7;
        x_sm_off[u] = (uint32_t)(row * 128 + ((c ^ (row & 7)) << 4));
        x_g_off[u]  = (uint32_t)(row * (IN_DIM * 2) + c * 16);
    }
    #pragma unroll
    for (int u = 0; u < 2; u++) {
        int f = tid + u * 256;
        int row = f >> 3, c = f & 7;
        w_sm_off[u] = (uint32_t)(row * 128 + ((c ^ (row & 7)) << 4));
        w_g_off[u]  = (uint32_t)(row * 128 + c * 16);
    }

    // ---- per-lane ldmatrix (read-side) components ----
    const int m7   = lane & 7;
    const int a_hi = lane >> 4;                       // A col-half
    const int rA0  = wm * 32 + (lane & 15);           // fm=0 row; fm=1 adds 16
    const int g    = lane >> 3;
    const int b_hi = g & 1;                           // B col-half
    const int rB0  = wn * 32 + (g >> 1) * 8 + m7;

    const char* x_base = (const char*)(g_x16 + (size_t)n0 * IN_DIM);

    // issue the 6 LDGSTS for one block into stage `st`
    auto issue_stage = [&](int st, int k) {
        const int cb = col_idx[k];
        const uint32_t sb = smem_u32 + (uint32_t)st * STAGE_BYTES;
        const char* x_g = x_base + (uint32_t)cb * (BS * 2);
        const char* w_g = (const char*)g_w16 + (uint32_t)k * (BS * BS * 2);
        #pragma unroll
        for (int u = 0; u < 4; u++)
            cp16(sb + OFF_X + x_sm_off[u], x_g + x_g_off[u]);
        #pragma unroll
        for (int u = 0; u < 2; u++)
            cp16(sb + OFF_W + w_sm_off[u], w_g + w_g_off[u]);
    };

    // ---- prologue: fill 2 stages ahead ----
    {
        int pre = cnt < 2 ? cnt : 2;
        for (int i = 0; i < pre; i++) { issue_stage(i, list[i]); CP_COMMIT(); }
    }

    // stage index cycling (avoid % in loop)
    int st = 0;                         // stage of iter `it`
    int st_next = (NSTAGE > 2) ? 2 : 0; // stage of iter `it+2` (issue slot)

    for (int it = 0; it < cnt; it++) {
        if (it + 1 < cnt) CP_WAIT(1); else CP_WAIT(0);
        __syncthreads();                // publishes stage `it`; also fences
                                        // prior readers of the re-fill slot
        if (it + 2 < cnt) {
            issue_stage(st_next, list[it + 2]);
            CP_COMMIT();
        }

        const uint32_t sb = smem_u32 + (uint32_t)st * STAGE_BYTES;
        const uint32_t sx = sb + OFF_X, sw = sb + OFF_W;

        #pragma unroll
        for (int kk = 0; kk < 4; kk++) {
            uint32_t a[2][4], b[4][2];
            const uint32_t aswz = (uint32_t)((((kk << 1) | a_hi) ^ m7) << 4);
            const uint32_t bswz = (uint32_t)((((kk << 1) | b_hi) ^ m7) << 4);
            #pragma unroll
            for (int fm = 0; fm < 2; fm++) {
                uint32_t ao = (uint32_t)((rA0 + fm * 16) * 128) + aswz;
                LDSM4(a[fm][0], a[fm][1], a[fm][2], a[fm][3], sx + ao);
            }
            #pragma unroll
            for (int j = 0; j < 4; j += 2) {
                uint32_t bo = (uint32_t)((rB0 + j * 8) * 128) + bswz;
                LDSM4(b[j][0], b[j][1], b[j + 1][0], b[j + 1][1], sw + bo);
            }
            #pragma unroll
            for (int fm = 0; fm < 2; fm++)
                #pragma unroll
                for (int fn = 0; fn < 4; fn++)
                    MMA16816(acc[fm][fn], a[fm], b[fn][0], b[fn][1]);
        }

        st      = (st == NSTAGE - 1) ? 0 : st + 1;
        st_next = (st_next == NSTAGE - 1) ? 0 : st_next + 1;
    }

    // ---- store (every element written: handles poison + bias-only rows) ----
    #pragma unroll
    for (int fm = 0; fm < 2; fm++) {
        int mrow = n0 + wm * 32 + fm * 16 + (lane >> 2);
        #pragma unroll
        for (int fn = 0; fn < 4; fn++) {
            int ncol = r * BS + wn * 32 + fn * 8 + (lane & 3) * 2;
            float2 v0 = make_float2(acc[fm][fn][0], acc[fm][fn][1]);
            float2 v1 = make_float2(acc[fm][fn][2], acc[fm][fn][3]);
            *(float2*)(y + (size_t)mrow * OUT_DIM + ncol)       = v0;
            *(float2*)(y + (size_t)(mrow + 8) * OUT_DIM + ncol) = v1;
        }
    }
}

extern "C" void kernel_launch(void* const* d_in, const int* in_sizes, int n_in,
                              void* d_out, int out_size) {
    (void)in_sizes; (void)n_in; (void)out_size;
    const float* x       = (const float*)d_in[0];
    const float* blocks  = (const float*)d_in[1];
    const float* bias    = (const float*)d_in[2];
    const int*   row_idx = (const int*)d_in[3];
    const int*   col_idx = (const int*)d_in[4];
    float*       y       = (float*)d_out;

    // Fused setup: binning runs in blocks [0,64) concurrently with the
    // DRAM-bound conversion in the remaining blocks (one launch).
    setup_kernel<<<NROWBLK + CONV_BLOCKS, 256>>>(x, blocks, row_idx);

    cudaFuncSetAttribute(bsl_mma_kernel,
                         cudaFuncAttributeMaxDynamicSharedMemorySize, SMEM_TOTAL);

    dim3 grid(N_DIM / TM, NROWBLK);
    bsl_mma_kernel<<<grid, 256, SMEM_TOTAL>>>(bias, col_idx, y);
}

// round 13
// speedup vs baseline: 10.4935x; 1.0914x over previous
#include <cuda_runtime.h>
#include <cuda_fp16.h>
#include <cstdint>

// Problem constants (fixed shapes per reference)
#define K_BLOCKS 1024
#define NROWBLK  64      // OUT / BS
#define BS       64
#define TM       128     // N-rows per CTA tile
#define IN_DIM   4096
#define OUT_DIM  4096
#define N_DIM    4096

// Per-stage smem layout (bytes). Rows are exactly 128B -> SW128 XOR swizzle.
#define OFF_X    0
#define OFF_W    16384
#define STAGE_BYTES 24576            // 24 KB
#define NSTAGE   3
#define SMEM_TOTAL  (NSTAGE * STAGE_BYTES)  // 72 KB -> 3 CTAs/SM

// ---------------- scratch (__device__ globals; no allocs allowed) ----------------
__device__ int g_row_cnt[NROWBLK];
__device__ int g_row_list[NROWBLK * K_BLOCKS];
__device__ __half g_x16[(size_t)N_DIM * IN_DIM];
__device__ __half g_w16[(size_t)K_BLOCKS * BS * BS];

// ---------------- fused setup: binning (blocks 0..63) + f32->fp16 convert ----------------
#define NX4 ((size_t)N_DIM * IN_DIM / 4)                 // float4 groups in x
#define NW4 ((size_t)K_BLOCKS * BS * BS / 4)             // float4 groups in w
#define CONV_BLOCKS ((unsigned)((NX4 + NW4 + 255) / 256))

__global__ void setup_kernel(const float* __restrict__ x,
                             const float* __restrict__ w,
                             const int* __restrict__ row_idx) {
    if (blockIdx.x < NROWBLK) {
        // ---- per-row binning; warp 0 only. Overlaps with conversion blocks. ----
        if (threadIdx.x >= 32) return;
        int r = blockIdx.x;
        int lane = threadIdx.x;
        int cnt = 0;
        for (int base = 0; base < K_BLOCKS; base += 32) {
            int k = base + lane;
            int v = row_idx[k];
            unsigned m = __ballot_sync(0xffffffffu, v == r);
            if (v == r) {
                int pos = __popc(m & ((1u << lane) - 1u));
                g_row_list[r * K_BLOCKS + cnt + pos] = k;
            }
            cnt += __popc(m);
        }
        if (lane == 0) g_row_cnt[r] = cnt;
        return;
    }
    // ---- conversion: x plane then w plane ----
    size_t g = (size_t)(blockIdx.x - NROWBLK) * blockDim.x + threadIdx.x;
    const float* src;
    __half* dst;
    size_t i;
    if (g < NX4)            { src = x; dst = g_x16; i = g * 4; }
    else if (g < NX4 + NW4) { src = w; dst = g_w16; i = (g - NX4) * 4; }
    else return;
    float4 v = *(const float4*)(src + i);
    __half h[4];
    h[0] = __float2half(v.x); h[1] = __float2half(v.y);
    h[2] = __float2half(v.z); h[3] = __float2half(v.w);
    *(uint2*)(dst + i) = *(uint2*)h;
}

// ---------------- PTX helpers ----------------
__device__ __forceinline__ void cp16(uint32_t saddr, const void* gptr) {
    asm volatile("cp.async.cg.shared.global [%0], [%1], 16;\n"
                 :: "r"(saddr), "l"(gptr));
}
#define CP_COMMIT() asm volatile("cp.async.commit_group;\n" ::: "memory")
#define CP_WAIT(n)  asm volatile("cp.async.wait_group %0;\n" :: "n"(n) : "memory")

#define LDSM4(R0, R1, R2, R3, ADDR)                                              \
    asm volatile("ldmatrix.sync.aligned.m8n8.x4.shared.b16 {%0,%1,%2,%3}, [%4];" \
                 : "=r"(R0), "=r"(R1), "=r"(R2), "=r"(R3) : "r"(ADDR))

#define MMA16816(C, A, B0, B1)                                                  \
    asm volatile("mma.sync.aligned.m16n8k16.row.col.f32.f16.f16.f32 "           \
                 "{%0,%1,%2,%3}, {%4,%5,%6,%7}, {%8,%9}, {%0,%1,%2,%3};"        \
                 : "+f"((C)[0]), "+f"((C)[1]), "+f"((C)[2]), "+f"((C)[3])       \
                 : "r"((A)[0]), "r"((A)[1]), "r"((A)[2]), "r"((A)[3]),          \
                   "r"(B0), "r"(B1))

extern __shared__ __align__(1024) char smem_raw[];

// grid = (N/TM, NROWBLK), block = 128 (4 warps, each owns a 32m x 64n tile).
// Warp layout 4(m) x 1(n): LDS per iter = A 16KB(1x... 4x4KB) + B 32KB + STS 24KB
// = 72KB vs 88KB for the old 4x2 layout.
__global__ __launch_bounds__(128, 3) void bsl_mma_kernel(
    const float* __restrict__ bias,
    const int* __restrict__ col_idx,
    float* __restrict__ y)
{
    const int r    = blockIdx.y;
    const int n0   = blockIdx.x * TM;
    const int tid  = threadIdx.x;
    const int wm   = tid >> 5;   // warp row (m): 32 rows each
    const int lane = tid & 31;

    const int cnt   = g_row_cnt[r];
    const int* list = g_row_list + r * K_BLOCKS;

    const uint32_t smem_u32 = (uint32_t)__cvta_generic_to_shared(smem_raw);

    // ---- accumulators [fm][fn][4]: init with bias (depends only on out col) ----
    float acc[2][8][4];
    #pragma unroll
    for (int fn = 0; fn < 8; fn++) {
        int ncol = r * BS + fn * 8 + (lane & 3) * 2;
        float b0 = bias[ncol], b1 = bias[ncol + 1];
        #pragma unroll
        for (int fm = 0; fm < 2; fm++) {
            acc[fm][fn][0] = b0; acc[fm][fn][1] = b1;
            acc[fm][fn][2] = b0; acc[fm][fn][3] = b1;
        }
    }

    // ---- per-lane cp.async offsets (u32 byte offsets; SW128, 128B rows) ----
    // x: 1024 16B chunks (128 rows x 8), 8/thread. w: 512 chunks, 4/thread.
    uint32_t x_sm_off[8], x_g_off[8], w_sm_off[4], w_g_off[4];
    #pragma unroll
    for (int u = 0; u < 8; u++) {
        int f = tid + u * 128;
        int row = f >> 3, c = f & 7;
        x_sm_off[u] = (uint32_t)(row * 128 + ((c ^ (row & 7)) << 4));
        x_g_off[u]  = (uint32_t)(row * (IN_DIM * 2) + c * 16);
    }
    #pragma unroll
    for (int u = 0; u < 4; u++) {
        int f = tid + u * 128;
        int row = f >> 3, c = f & 7;
        w_sm_off[u] = (uint32_t)(row * 128 + ((c ^ (row & 7)) << 4));
        w_g_off[u]  = (uint32_t)(row * 128 + c * 16);
    }

    // ---- per-lane ldmatrix (read-side) components ----
    const int m7   = lane & 7;
    const int a_hi = lane >> 4;                       // A col-half
    const int rA0  = wm * 32 + (lane & 15);           // fm=0 row; fm=1 adds 16
    const int g    = lane >> 3;
    const int b_hi = g & 1;                           // B col-half
    const int rB0  = (g >> 1) * 8 + m7;               // pair p adds p*16 rows

    const char* x_base = (const char*)(g_x16 + (size_t)n0 * IN_DIM);

    // issue the 12 LDGSTS for one block into stage `st`
    auto issue_stage = [&](int st, int k) {
        const int cb = col_idx[k];
        const uint32_t sb = smem_u32 + (uint32_t)st * STAGE_BYTES;
        const char* x_g = x_base + (uint32_t)cb * (BS * 2);
        const char* w_g = (const char*)g_w16 + (uint32_t)k * (BS * BS * 2);
        #pragma unroll
        for (int u = 0; u < 8; u++)
            cp16(sb + OFF_X + x_sm_off[u], x_g + x_g_off[u]);
        #pragma unroll
        for (int u = 0; u < 4; u++)
            cp16(sb + OFF_W + w_sm_off[u], w_g + w_g_off[u]);
    };

    // ---- prologue: fill 2 stages ahead ----
    {
        int pre = cnt < 2 ? cnt : 2;
        for (int i = 0; i < pre; i++) { issue_stage(i, list[i]); CP_COMMIT(); }
    }

    // stage index cycling (avoid % in loop)
    int st = 0;                         // stage of iter `it`
    int st_next = 2;                    // stage of iter `it+2` (issue slot)

    for (int it = 0; it < cnt; it++) {
        if (it + 1 < cnt) CP_WAIT(1); else CP_WAIT(0);
        __syncthreads();                // publishes stage `it`; also fences
                                        // prior readers of the re-fill slot
        if (it + 2 < cnt) {
            issue_stage(st_next, list[it + 2]);
            CP_COMMIT();
        }

        const uint32_t sb = smem_u32 + (uint32_t)st * STAGE_BYTES;
        const uint32_t sx = sb + OFF_X, sw = sb + OFF_W;

        #pragma unroll
        for (int kk = 0; kk < 4; kk++) {
            uint32_t a[2][4], b[8][2];
            const uint32_t aswz = (uint32_t)((((kk << 1) | a_hi) ^ m7) << 4);
            const uint32_t bswz = (uint32_t)((((kk << 1) | b_hi) ^ m7) << 4);
            #pragma unroll
            for (int fm = 0; fm < 2; fm++) {
                uint32_t ao = (uint32_t)((rA0 + fm * 16) * 128) + aswz;
                LDSM4(a[fm][0], a[fm][1], a[fm][2], a[fm][3], sx + ao);
            }
            #pragma unroll
            for (int p = 0; p < 4; p++) {   // pairs (fn=2p, 2p+1)
                uint32_t bo = (uint32_t)((rB0 + p * 16) * 128) + bswz;
                LDSM4(b[2 * p][0], b[2 * p][1], b[2 * p + 1][0], b[2 * p + 1][1],
                      sw + bo);
            }
            #pragma unroll
            for (int fm = 0; fm < 2; fm++)
                #pragma unroll
                for (int fn = 0; fn < 8; fn++)
                    MMA16816(acc[fm][fn], a[fm], b[fn][0], b[fn][1]);
        }

        st      = (st == NSTAGE - 1) ? 0 : st + 1;
        st_next = (st_next == NSTAGE - 1) ? 0 : st_next + 1;
    }

    // ---- store (every element written: handles poison + bias-only rows) ----
    #pragma unroll
    for (int fm = 0; fm < 2; fm++) {
        int mrow = n0 + wm * 32 + fm * 16 + (lane >> 2);
        #pragma unroll
        for (int fn = 0; fn < 8; fn++) {
            int ncol = r * BS + fn * 8 + (lane & 3) * 2;
            float2 v0 = make_float2(acc[fm][fn][0], acc[fm][fn][1]);
            float2 v1 = make_float2(acc[fm][fn][2], acc[fm][fn][3]);
            *(float2*)(y + (size_t)mrow * OUT_DIM + ncol)       = v0;
            *(float2*)(y + (size_t)(mrow + 8) * OUT_DIM + ncol) = v1;
        }
    }
}

extern "C" void kernel_launch(void* const* d_in, const int* in_sizes, int n_in,
                              void* d_out, int out_size) {
    (void)in_sizes; (void)n_in; (void)out_size;
    const float* x       = (const float*)d_in[0];
    const float* blocks  = (const float*)d_in[1];
    const float* bias    = (const float*)d_in[2];
    const int*   row_idx = (const int*)d_in[3];
    const int*   col_idx = (const int*)d_in[4];
    float*       y       = (float*)d_out;

    // Fused setup: binning runs in blocks [0,64) concurrently with the
    // DRAM-bound conversion in the remaining blocks (one launch).
    setup_kernel<<<NROWBLK + CONV_BLOCKS, 256>>>(x, blocks, row_idx);

    cudaFuncSetAttribute(bsl_mma_kernel,
                         cudaFuncAttributeMaxDynamicSharedMemorySize, SMEM_TOTAL);

    dim3 grid(N_DIM / TM, NROWBLK);
    bsl_mma_kernel<<<grid, 128, SMEM_TOTAL>>>(bias, col_idx, y);
}

// round 15
// speedup vs baseline: 10.8551x; 1.0345x over previous
#include <cuda_runtime.h>
#include <cuda_fp16.h>
#include <cstdint>

// Problem constants (fixed shapes per reference)
#define K_BLOCKS 1024
#define NROWBLK  64      // OUT / BS
#define BS       64
#define TM       128     // N-rows per CTA tile
#define IN_DIM   4096
#define OUT_DIM  4096
#define N_DIM    4096

// Per-stage smem layout (bytes). Rows are exactly 128B -> SW128 XOR swizzle.
#define OFF_X    0
#define OFF_W    16384
#define STAGE_BYTES 24576            // 24 KB
#define NSTAGE   2
#define SMEM_TOTAL  (NSTAGE * STAGE_BYTES)  // 48 KB -> 4 CTAs/SM

// ---------------- scratch (__device__ globals; no allocs allowed) ----------------
__device__ int g_row_cnt[NROWBLK];
__device__ int g_row_list[NROWBLK * K_BLOCKS];
__device__ __half g_x16[(size_t)N_DIM * IN_DIM];
__device__ __half g_w16[(size_t)K_BLOCKS * BS * BS];

// ---------------- fused setup: binning (blocks 0..63) + f32->fp16 convert ----------------
#define NX4 ((size_t)N_DIM * IN_DIM / 4)                 // float4 groups in x
#define NW4 ((size_t)K_BLOCKS * BS * BS / 4)             // float4 groups in w
#define CONV_BLOCKS ((unsigned)((NX4 + NW4 + 255) / 256))

__global__ void setup_kernel(const float* __restrict__ x,
                             const float* __restrict__ w,
                             const int* __restrict__ row_idx) {
    if (blockIdx.x < NROWBLK) {
        // ---- per-row binning; warp 0 only. Overlaps with conversion blocks. ----
        if (threadIdx.x >= 32) return;
        int r = blockIdx.x;
        int lane = threadIdx.x;
        int cnt = 0;
        for (int base = 0; base < K_BLOCKS; base += 32) {
            int k = base + lane;
            int v = row_idx[k];
            unsigned m = __ballot_sync(0xffffffffu, v == r);
            if (v == r) {
                int pos = __popc(m & ((1u << lane) - 1u));
                g_row_list[r * K_BLOCKS + cnt + pos] = k;
            }
            cnt += __popc(m);
        }
        if (lane == 0) g_row_cnt[r] = cnt;
        return;
    }
    // ---- conversion: x plane then w plane ----
    size_t g = (size_t)(blockIdx.x - NROWBLK) * blockDim.x + threadIdx.x;
    const float* src;
    __half* dst;
    size_t i;
    if (g < NX4)            { src = x; dst = g_x16; i = g * 4; }
    else if (g < NX4 + NW4) { src = w; dst = g_w16; i = (g - NX4) * 4; }
    else return;
    float4 v = *(const float4*)(src + i);
    __half h[4];
    h[0] = __float2half(v.x); h[1] = __float2half(v.y);
    h[2] = __float2half(v.z); h[3] = __float2half(v.w);
    *(uint2*)(dst + i) = *(uint2*)h;
}

// ---------------- PTX helpers ----------------
__device__ __forceinline__ void cp16(uint32_t saddr, const void* gptr) {
    asm volatile("cp.async.cg.shared.global [%0], [%1], 16;\n"
                 :: "r"(saddr), "l"(gptr));
}
#define CP_COMMIT() asm volatile("cp.async.commit_group;\n" ::: "memory")
#define CP_WAIT(n)  asm volatile("cp.async.wait_group %0;\n" :: "n"(n) : "memory")

#define LDSM4(R0, R1, R2, R3, ADDR)                                              \
    asm volatile("ldmatrix.sync.aligned.m8n8.x4.shared.b16 {%0,%1,%2,%3}, [%4];" \
                 : "=r"(R0), "=r"(R1), "=r"(R2), "=r"(R3) : "r"(ADDR))

#define MMA16816(C, A, B0, B1)                                                  \
    asm volatile("mma.sync.aligned.m16n8k16.row.col.f32.f16.f16.f32 "           \
                 "{%0,%1,%2,%3}, {%4,%5,%6,%7}, {%8,%9}, {%0,%1,%2,%3};"        \
                 : "+f"((C)[0]), "+f"((C)[1]), "+f"((C)[2]), "+f"((C)[3])       \
                 : "r"((A)[0]), "r"((A)[1]), "r"((A)[2]), "r"((A)[3]),          \
                   "r"(B0), "r"(B1))

extern __shared__ __align__(1024) char smem_raw[];

// grid = (N/TM, NROWBLK), block = 128 (4 warps, each owns a 32m x 64n tile).
// 2 stages x 24KB = 48KB smem; regs capped at 128 -> 4 CTAs/SM (16 warps).
__global__ __launch_bounds__(128, 4) void bsl_mma_kernel(
    const float* __restrict__ bias,
    const int* __restrict__ col_idx,
    float* __restrict__ y)
{
    const int r    = blockIdx.y;
    const int n0   = blockIdx.x * TM;
    const int tid  = threadIdx.x;
    const int wm   = tid >> 5;   // warp row (m): 32 rows each
    const int lane = tid & 31;

    const int cnt   = g_row_cnt[r];
    const int* list = g_row_list + r * K_BLOCKS;

    const uint32_t smem_u32 = (uint32_t)__cvta_generic_to_shared(smem_raw);

    // ---- accumulators [fm][fn][4]: init with bias (depends only on out col) ----
    float acc[2][8][4];
    #pragma unroll
    for (int fn = 0; fn < 8; fn++) {
        int ncol = r * BS + fn * 8 + (lane & 3) * 2;
        float b0 = bias[ncol], b1 = bias[ncol + 1];
        #pragma unroll
        for (int fm = 0; fm < 2; fm++) {
            acc[fm][fn][0] = b0; acc[fm][fn][1] = b1;
            acc[fm][fn][2] = b0; acc[fm][fn][3] = b1;
        }
    }

    // ---- per-lane ldmatrix (read-side) components ----
    const int m7   = lane & 7;
    const int a_hi = lane >> 4;                       // A col-half
    const int rA0  = wm * 32 + (lane & 15);           // fm=0 row; fm=1 adds 16
    const int g    = lane >> 3;
    const int b_hi = g & 1;                           // B col-half
    const int rB0  = (g >> 1) * 8 + m7;               // pair p adds p*16 rows

    const char* x_base = (const char*)(g_x16 + (size_t)n0 * IN_DIM);
    const char* w_base = (const char*)g_w16;

    // issue the 12 LDGSTS for one block into stage `st`.
    // Offsets recomputed from tid each call (saves ~24 live registers; the
    // ALU pipe has headroom at 8%).
    auto issue_stage = [&](int st, int k) {
        const int cb = col_idx[k];
        const uint32_t sb = smem_u32 + (uint32_t)st * STAGE_BYTES;
        const char* x_g = x_base + (uint32_t)cb * (BS * 2);
        const char* w_g = w_base + (uint32_t)k * (BS * BS * 2);
        #pragma unroll
        for (int u = 0; u < 8; u++) {
            int f = tid + u * 128;
            int row = f >> 3, c = f & 7;
            uint32_t smo = (uint32_t)(row * 128 + ((c ^ (row & 7)) << 4));
            uint32_t go  = (uint32_t)(row * (IN_DIM * 2) + c * 16);
            cp16(sb + OFF_X + smo, x_g + go);
        }
        #pragma unroll
        for (int u = 0; u < 4; u++) {
            int f = tid + u * 128;
            int row = f >> 3, c = f & 7;
            uint32_t smo = (uint32_t)(row * 128 + ((c ^ (row & 7)) << 4));
            uint32_t go  = (uint32_t)(row * 128 + c * 16);
            cp16(sb + OFF_W + smo, w_g + go);
        }
    };

    // ---- prologue: fill stage 0 ----
    if (cnt > 0) { issue_stage(0, list[0]); CP_COMMIT(); }

    for (int it = 0; it < cnt; it++) {
        const int st = it & 1;
        CP_WAIT(0);                     // stage `st` data landed
        __syncthreads();                // all warps see it; prior readers of
                                        // the other stage are done
        if (it + 1 < cnt) {
            issue_stage(st ^ 1, list[it + 1]);
            CP_COMMIT();
        }

        const uint32_t sb = smem_u32 + (uint32_t)st * STAGE_BYTES;
        const uint32_t sx = sb + OFF_X, sw = sb + OFF_W;

        #pragma unroll
        for (int kk = 0; kk < 4; kk++) {
            uint32_t a[2][4], b[8][2];
            const uint32_t aswz = (uint32_t)((((kk << 1) | a_hi) ^ m7) << 4);
            const uint32_t bswz = (uint32_t)((((kk << 1) | b_hi) ^ m7) << 4);
            #pragma unroll
            for (int fm = 0; fm < 2; fm++) {
                uint32_t ao = (uint32_t)((rA0 + fm * 16) * 128) + aswz;
                LDSM4(a[fm][0], a[fm][1], a[fm][2], a[fm][3], sx + ao);
            }
            #pragma unroll
            for (int p = 0; p < 4; p++) {   // pairs (fn=2p, 2p+1)
                uint32_t bo = (uint32_t)((rB0 + p * 16) * 128) + bswz;
                LDSM4(b[2 * p][0], b[2 * p][1], b[2 * p + 1][0], b[2 * p + 1][1],
                      sw + bo);
            }
            #pragma unroll
            for (int fm = 0; fm < 2; fm++)
                #pragma unroll
                for (int fn = 0; fn < 8; fn++)
                    MMA16816(acc[fm][fn], a[fm], b[fn][0], b[fn][1]);
        }
    }

    // ---- store (every element written: handles poison + bias-only rows) ----
    #pragma unroll
    for (int fm = 0; fm < 2; fm++) {
        int mrow = n0 + wm * 32 + fm * 16 + (lane >> 2);
        #pragma unroll
        for (int fn = 0; fn < 8; fn++) {
            int ncol = r * BS + fn * 8 + (lane & 3) * 2;
            float2 v0 = make_float2(acc[fm][fn][0], acc[fm][fn][1]);
            float2 v1 = make_float2(acc[fm][fn][2], acc[fm][fn][3]);
            *(float2*)(y + (size_t)mrow * OUT_DIM + ncol)       = v0;
            *(float2*)(y + (size_t)(mrow + 8) * OUT_DIM + ncol) = v1;
        }
    }
}

extern "C" void kernel_launch(void* const* d_in, const int* in_sizes, int n_in,
                              void* d_out, int out_size) {
    (void)in_sizes; (void)n_in; (void)out_size;
    const float* x       = (const float*)d_in[0];
    const float* blocks  = (const float*)d_in[1];
    const float* bias    = (const float*)d_in[2];
    const int*   row_idx = (const int*)d_in[3];
    const int*   col_idx = (const int*)d_in[4];
    float*       y       = (float*)d_out;

    // Fused setup: binning runs in blocks [0,64) concurrently with the
    // DRAM-bound conversion in the remaining blocks (one launch).
    setup_kernel<<<NROWBLK + CONV_BLOCKS, 256>>>(x, blocks, row_idx);

    cudaFuncSetAttribute(bsl_mma_kernel,
                         cudaFuncAttributeMaxDynamicSharedMemorySize, SMEM_TOTAL);

    dim3 grid(N_DIM / TM, NROWBLK);
    bsl_mma_kernel<<<grid, 128, SMEM_TOTAL>>>(bias, col_idx, y);
}